// round 2
// baseline (speedup 1.0000x reference)
#include <cuda_runtime.h>
#include <cuda_bf16.h>
#include <cstdint>
#include <cstdio>

// ---------------- problem constants ----------------
#define N_NEURONS 80
#define TBL       256
#define LATENT    128
#define N_GRAPHS  64
#define N_NODES   (N_GRAPHS * N_NEURONS)   // 5120
#define N_EDGES   (N_NODES * 32)           // 163840
#define N2        (N_NEURONS * N_NEURONS)  // 6400
#define HID       (2 * N2)                 // 12800

// ---------------- device scratch (no allocations allowed) ----------------
__device__ float d_H[N_NODES * LATENT];     // x @ Wg
__device__ float d_AGG[N_NODES * LATENT];   // scatter accumulation
__device__ int   d_DEG[N_NODES];
__device__ float d_DINV[N_NODES];
__device__ float d_ZOUT[N_GRAPHS * N2];     // outer products [64, 6400]
__device__ float d_Z2[N_GRAPHS * HID];      // hidden layer [64, 12800]

// ---------------- PTX helpers ----------------
__device__ __forceinline__ uint32_t cvt_tf32(float x) {
    uint32_t r;
    asm("cvt.rna.tf32.f32 %0, %1;" : "=r"(r) : "f"(x));
    return r;
}

__device__ __forceinline__ void mma_tf32(float c[4],
                                         uint32_t a0, uint32_t a1, uint32_t a2, uint32_t a3,
                                         uint32_t b0, uint32_t b1) {
    asm volatile(
        "mma.sync.aligned.m16n8k8.row.col.f32.tf32.tf32.f32 "
        "{%0,%1,%2,%3},{%4,%5,%6,%7},{%8,%9},{%0,%1,%2,%3};"
        : "+f"(c[0]), "+f"(c[1]), "+f"(c[2]), "+f"(c[3])
        : "r"(a0), "r"(a1), "r"(a2), "r"(a3), "r"(b0), "r"(b1));
}

__device__ __forceinline__ void cp_async16(void* smem_dst, const void* gmem_src) {
    uint32_t s = (uint32_t)__cvta_generic_to_shared(smem_dst);
    asm volatile("cp.async.cg.shared.global [%0], [%1], 16;" :: "r"(s), "l"(gmem_src));
}
__device__ __forceinline__ void cp_commit() { asm volatile("cp.async.commit_group;"); }
template <int NN>
__device__ __forceinline__ void cp_wait() { asm volatile("cp.async.wait_group %0;" :: "n"(NN)); }

// ---------------- small kernels ----------------
__global__ void zero_kernel(float* __restrict__ agg, int* __restrict__ deg) {
    int i = blockIdx.x * blockDim.x + threadIdx.x;
    if (i < N_NODES * LATENT) agg[i] = 0.0f;
    if (i < N_NODES) deg[i] = 0;
}

__global__ void deg_kernel(const int* __restrict__ dst, int* __restrict__ deg) {
    int i = blockIdx.x * blockDim.x + threadIdx.x;
    if (i < N_EDGES) atomicAdd(&deg[dst[i]], 1);
}

__global__ void dinv_kernel(const int* __restrict__ deg, float* __restrict__ dinv) {
    int i = blockIdx.x * blockDim.x + threadIdx.x;
    if (i < N_NODES) {
        int d = deg[i];
        dinv[i] = (d > 0) ? rsqrtf((float)d) : 0.0f;
    }
}

// one warp per edge: agg[dst] += h[src] * dinv[src]*dinv[dst]  (float4 per lane)
__global__ void __launch_bounds__(256) scatter_kernel(
    const float* __restrict__ H, const int* __restrict__ src, const int* __restrict__ dst,
    const float* __restrict__ dinv, float* __restrict__ agg) {
    int e = (blockIdx.x * blockDim.x + threadIdx.x) >> 5;
    int lane = threadIdx.x & 31;
    if (e >= N_EDGES) return;
    int s = src[e], d = dst[e];
    float nrm = dinv[s] * dinv[d];
    const float4* hp = reinterpret_cast<const float4*>(H + (size_t)s * LATENT);
    float4 v = hp[lane];
    v.x *= nrm; v.y *= nrm; v.z *= nrm; v.w *= nrm;
    float* ap = agg + (size_t)d * LATENT + lane * 4;
    asm volatile("red.global.add.v4.f32 [%0], {%1,%2,%3,%4};"
                 :: "l"(ap), "f"(v.x), "f"(v.y), "f"(v.z), "f"(v.w) : "memory");
}

__global__ void relu_bias_kernel(float* __restrict__ agg, const float* __restrict__ bg) {
    int i = blockIdx.x * blockDim.x + threadIdx.x;
    if (i < N_NODES * LATENT) {
        float v = agg[i] + bg[i & (LATENT - 1)];
        agg[i] = fmaxf(v, 0.0f);
    }
}

// per-graph z_b @ z_b^T : 64 blocks, 256 threads, 5x5 register tiles
__global__ void __launch_bounds__(256) outer_kernel(const float* __restrict__ Z,
                                                    float* __restrict__ Zo) {
    __shared__ float zs[N_NEURONS][LATENT + 1];  // pad -> bank-conflict free
    int b = blockIdx.x;
    const float* zb = Z + (size_t)b * N_NEURONS * LATENT;
    for (int i = threadIdx.x; i < N_NEURONS * LATENT; i += 256) {
        zs[i >> 7][i & 127] = zb[i];
    }
    __syncthreads();
    int tx = threadIdx.x & 15, ty = threadIdx.x >> 4;
    int nB = ty * 5, mB = tx * 5;
    float acc[5][5] = {};
    for (int l = 0; l < LATENT; l++) {
        float zn[5], zm[5];
#pragma unroll
        for (int i = 0; i < 5; i++) { zn[i] = zs[nB + i][l]; zm[i] = zs[mB + i][l]; }
#pragma unroll
        for (int i = 0; i < 5; i++)
#pragma unroll
            for (int j = 0; j < 5; j++) acc[i][j] = fmaf(zn[i], zm[j], acc[i][j]);
    }
    float* ob = Zo + (size_t)b * N2;
#pragma unroll
    for (int i = 0; i < 5; i++)
#pragma unroll
        for (int j = 0; j < 5; j++)
            ob[(nB + i) * N_NEURONS + mB + j] = acc[i][j];
}

// ---------------- tf32 GEMM: C[M,N] = act(A[M,K] @ W[K,N] + bias) ----------------
// 64x64 block tile, 256 threads (8 warps in 4x2), k-step 32, cp.async double buffer.
// ACT: 0 = none, 1 = relu, 2 = sigmoid
template <int K, int N, int ACT>
__global__ void __launch_bounds__(256) gemm64_tf32(
    const float* __restrict__ A, const float* __restrict__ W,
    const float* __restrict__ bias, float* __restrict__ C) {
    constexpr int KT = K / 32;
    __shared__ __align__(16) float As[2][64][36];   // 64 rows x 32 k (row stride 144B, 16B-mult)
    __shared__ __align__(16) float Ws[2][32][72];   // 32 k x 64 n (row stride 288B, 16B-mult)

    const int t = threadIdx.x;
    const int m0 = blockIdx.y * 64;
    const int n0 = blockIdx.x * 64;

    const int lane = t & 31, wid = t >> 5;
    const int g = lane >> 2, q = lane & 3;
    const int wm = (wid >> 1) << 4;   // 4 m-warps: rows wm..wm+15
    const int wn = (wid & 1) << 5;    // 2 n-warps: cols wn..wn+31

    // A tile: 64 rows x 32 floats = 512 16B chunks; 256 threads x 2
    auto loadA = [&](int buf, int kt) {
#pragma unroll
        for (int i = 0; i < 2; i++) {
            int id = t + i * 256;
            int r = id >> 3, c = id & 7;   // 64 rows x 8 chunks
            cp_async16(&As[buf][r][c * 4], A + (size_t)(m0 + r) * K + kt * 32 + c * 4);
        }
    };
    // W tile: 32 rows x 64 floats = 512 16B chunks; 256 threads x 2
    auto loadW = [&](int buf, int kt) {
#pragma unroll
        for (int i = 0; i < 2; i++) {
            int id = t + i * 256;
            int r = id >> 4, c = id & 15;  // 32 rows x 16 chunks
            cp_async16(&Ws[buf][r][c * 4], W + (size_t)(kt * 32 + r) * N + n0 + c * 4);
        }
    };

    float acc[4][4] = {};

    loadA(0, 0); loadW(0, 0); cp_commit();

    for (int kt = 0; kt < KT; kt++) {
        if (kt + 1 < KT) {
            loadA((kt + 1) & 1, kt + 1);
            loadW((kt + 1) & 1, kt + 1);
            cp_commit();
            cp_wait<1>();
        } else {
            cp_wait<0>();
        }
        __syncthreads();

        const int bb = kt & 1;
#pragma unroll
        for (int kk = 0; kk < 4; kk++) {
            const int k8 = kk * 8;
            uint32_t a0 = cvt_tf32(As[bb][wm + g][k8 + q]);
            uint32_t a1 = cvt_tf32(As[bb][wm + g + 8][k8 + q]);
            uint32_t a2 = cvt_tf32(As[bb][wm + g][k8 + q + 4]);
            uint32_t a3 = cvt_tf32(As[bb][wm + g + 8][k8 + q + 4]);
#pragma unroll
            for (int nf = 0; nf < 4; nf++) {
                uint32_t b0 = cvt_tf32(Ws[bb][k8 + q][wn + nf * 8 + g]);
                uint32_t b1 = cvt_tf32(Ws[bb][k8 + q + 4][wn + nf * 8 + g]);
                mma_tf32(acc[nf], a0, a1, a2, a3, b0, b1);
            }
        }
        __syncthreads();
    }

    // epilogue: c0:(g,2q) c1:(g,2q+1) c2:(g+8,2q) c3:(g+8,2q+1)
#pragma unroll
    for (int nf = 0; nf < 4; nf++) {
#pragma unroll
        for (int i = 0; i < 4; i++) {
            int row = m0 + wm + g + ((i >> 1) << 3);
            int col = n0 + wn + nf * 8 + q * 2 + (i & 1);
            float v = acc[nf][i];
            if (bias) v += bias[col];
            if (ACT == 1) v = fmaxf(v, 0.0f);
            else if (ACT == 2) v = 1.0f / (1.0f + expf(-v));
            C[(size_t)row * N + col] = v;
        }
    }
}

// ---------------- launch ----------------
extern "C" void kernel_launch(void* const* d_in, const int* in_sizes, int n_in,
                              void* d_out, int out_size) {
    const float* x   = (const float*)d_in[0];
    const int*   ei  = (const int*)d_in[1];
    const float* Wg  = (const float*)d_in[2];
    const float* bg  = (const float*)d_in[3];
    const float* W1  = (const float*)d_in[4];
    const float* b1  = (const float*)d_in[5];
    const float* W2  = (const float*)d_in[6];
    const float* b2  = (const float*)d_in[7];
    float* out = (float*)d_out;

    const int* src = ei;
    const int* dst = ei + N_EDGES;

    float *H, *AGG, *DINV, *ZOUT, *Z2;
    int* DEG;
    cudaGetSymbolAddress((void**)&H, d_H);
    cudaGetSymbolAddress((void**)&AGG, d_AGG);
    cudaGetSymbolAddress((void**)&DEG, d_DEG);
    cudaGetSymbolAddress((void**)&DINV, d_DINV);
    cudaGetSymbolAddress((void**)&ZOUT, d_ZOUT);
    cudaGetSymbolAddress((void**)&Z2, d_Z2);

    // 1. zero scratch accumulators (scratch persists across graph replays)
    zero_kernel<<<(N_NODES * LATENT + 255) / 256, 256>>>(AGG, DEG);

    // 2. in-degree + 3. dinv
    deg_kernel<<<(N_EDGES + 255) / 256, 256>>>(dst, DEG);
    dinv_kernel<<<(N_NODES + 255) / 256, 256>>>(DEG, DINV);

    // 4. h = x @ Wg   [5120,256]x[256,128]
    gemm64_tf32<TBL, LATENT, 0><<<dim3(LATENT / 64, N_NODES / 64), 256>>>(x, Wg, nullptr, H);

    // 5. scatter: agg[dst] += h[src] * norm
    scatter_kernel<<<N_EDGES / 8, 256>>>(H, src, dst, DINV, AGG);

    // 6. z = relu(agg + bg)
    relu_bias_kernel<<<(N_NODES * LATENT + 255) / 256, 256>>>(AGG, bg);

    // 7. per-graph outer products -> [64, 6400]
    outer_kernel<<<N_GRAPHS, 256>>>(AGG, ZOUT);

    // 8. z2 = relu(zout @ W1 + b1)   [64,6400]x[6400,12800]
    gemm64_tf32<N2, HID, 1><<<dim3(HID / 64, 1), 256>>>(ZOUT, W1, b1, Z2);

    // 9. y = sigmoid(z2 @ W2 + b2)   [64,12800]x[12800,6400]
    gemm64_tf32<HID, N2, 2><<<dim3(N2 / 64, 1), 256>>>(Z2, W2, b2, out);
}

// round 4
// speedup vs baseline: 1.6760x; 1.6760x over previous
#include <cuda_runtime.h>
#include <cuda_bf16.h>
#include <cstdint>
#include <cstdio>

// ---------------- problem constants ----------------
#define N_NEURONS 80
#define TBL       256
#define LATENT    128
#define N_GRAPHS  64
#define N_NODES   (N_GRAPHS * N_NEURONS)   // 5120
#define N_EDGES   (N_NODES * 32)           // 163840
#define N2        (N_NEURONS * N_NEURONS)  // 6400
#define HID       (2 * N2)                 // 12800

#define GSTAGES 4

// ---------------- device scratch (no allocations allowed) ----------------
__device__ float d_H[N_NODES * LATENT];     // x @ Wg
__device__ float d_AGG[N_NODES * LATENT];   // scatter accumulation
__device__ int   d_DEG[N_NODES];
__device__ float d_DINV[N_NODES];
__device__ float d_ZOUT[N_GRAPHS * N2];     // outer products [64, 6400]
__device__ float d_Z2[N_GRAPHS * HID];      // hidden layer [64, 12800]
__device__ float d_Z2P[4 * N_GRAPHS * HID]; // GEMM1 split-K partials
__device__ float d_OUTP[8 * N_GRAPHS * N2]; // GEMM2 split-K partials

// ---------------- PTX helpers ----------------
__device__ __forceinline__ uint32_t cvt_tf32(float x) {
    uint32_t r;
    asm("cvt.rna.tf32.f32 %0, %1;" : "=r"(r) : "f"(x));
    return r;
}

__device__ __forceinline__ void mma_tf32(float c[4],
                                         uint32_t a0, uint32_t a1, uint32_t a2, uint32_t a3,
                                         uint32_t b0, uint32_t b1) {
    asm volatile(
        "mma.sync.aligned.m16n8k8.row.col.f32.tf32.tf32.f32 "
        "{%0,%1,%2,%3},{%4,%5,%6,%7},{%8,%9},{%0,%1,%2,%3};"
        : "+f"(c[0]), "+f"(c[1]), "+f"(c[2]), "+f"(c[3])
        : "r"(a0), "r"(a1), "r"(a2), "r"(a3), "r"(b0), "r"(b1));
}

__device__ __forceinline__ void cp_async16(void* smem_dst, const void* gmem_src) {
    uint32_t s = (uint32_t)__cvta_generic_to_shared(smem_dst);
    asm volatile("cp.async.cg.shared.global [%0], [%1], 16;" :: "r"(s), "l"(gmem_src));
}
__device__ __forceinline__ void cp_commit() { asm volatile("cp.async.commit_group;"); }
template <int NN>
__device__ __forceinline__ void cp_wait() { asm volatile("cp.async.wait_group %0;" :: "n"(NN)); }

// ---------------- small kernels ----------------
__global__ void zero_kernel(float* __restrict__ agg, int* __restrict__ deg) {
    int i = blockIdx.x * blockDim.x + threadIdx.x;
    if (i < N_NODES * LATENT) agg[i] = 0.0f;
    if (i < N_NODES) deg[i] = 0;
}

__global__ void deg_kernel(const int* __restrict__ dst, int* __restrict__ deg) {
    int i = blockIdx.x * blockDim.x + threadIdx.x;
    if (i < N_EDGES) atomicAdd(&deg[dst[i]], 1);
}

__global__ void dinv_kernel(const int* __restrict__ deg, float* __restrict__ dinv) {
    int i = blockIdx.x * blockDim.x + threadIdx.x;
    if (i < N_NODES) {
        int d = deg[i];
        dinv[i] = (d > 0) ? rsqrtf((float)d) : 0.0f;
    }
}

// one warp per edge: agg[dst] += h[src] * dinv[src]*dinv[dst]  (float4 per lane)
__global__ void __launch_bounds__(256) scatter_kernel(
    const float* __restrict__ H, const int* __restrict__ src, const int* __restrict__ dst,
    const float* __restrict__ dinv, float* __restrict__ agg) {
    int e = (blockIdx.x * blockDim.x + threadIdx.x) >> 5;
    int lane = threadIdx.x & 31;
    if (e >= N_EDGES) return;
    int s = src[e], d = dst[e];
    float nrm = dinv[s] * dinv[d];
    const float4* hp = reinterpret_cast<const float4*>(H + (size_t)s * LATENT);
    float4 v = hp[lane];
    v.x *= nrm; v.y *= nrm; v.z *= nrm; v.w *= nrm;
    float* ap = agg + (size_t)d * LATENT + lane * 4;
    asm volatile("red.global.add.v4.f32 [%0], {%1,%2,%3,%4};"
                 :: "l"(ap), "f"(v.x), "f"(v.y), "f"(v.z), "f"(v.w) : "memory");
}

__global__ void relu_bias_kernel(float* __restrict__ agg, const float* __restrict__ bg) {
    int i = blockIdx.x * blockDim.x + threadIdx.x;
    if (i < N_NODES * LATENT) {
        float v = agg[i] + bg[i & (LATENT - 1)];
        agg[i] = fmaxf(v, 0.0f);
    }
}

// per-graph z_b @ z_b^T : 64 blocks, 256 threads, 5x5 register tiles
__global__ void __launch_bounds__(256) outer_kernel(const float* __restrict__ Z,
                                                    float* __restrict__ Zo) {
    __shared__ float zs[N_NEURONS][LATENT + 1];
    int b = blockIdx.x;
    const float* zb = Z + (size_t)b * N_NEURONS * LATENT;
    for (int i = threadIdx.x; i < N_NEURONS * LATENT; i += 256) {
        zs[i >> 7][i & 127] = zb[i];
    }
    __syncthreads();
    int tx = threadIdx.x & 15, ty = threadIdx.x >> 4;
    int nB = ty * 5, mB = tx * 5;
    float acc[5][5] = {};
    for (int l = 0; l < LATENT; l++) {
        float zn[5], zm[5];
#pragma unroll
        for (int i = 0; i < 5; i++) { zn[i] = zs[nB + i][l]; zm[i] = zs[mB + i][l]; }
#pragma unroll
        for (int i = 0; i < 5; i++)
#pragma unroll
            for (int j = 0; j < 5; j++) acc[i][j] = fmaf(zn[i], zm[j], acc[i][j]);
    }
    float* ob = Zo + (size_t)b * N2;
#pragma unroll
    for (int i = 0; i < 5; i++)
#pragma unroll
        for (int j = 0; j < 5; j++)
            ob[(nB + i) * N_NEURONS + mB + j] = acc[i][j];
}

// split-K reduction epilogue: out = act(sum_s P[s] + bias[col])
template <int SLICES, int NCOL, int ACT>
__global__ void epi_kernel(const float* __restrict__ P, const float* __restrict__ bias,
                           float* __restrict__ out, int total) {
    int i = blockIdx.x * blockDim.x + threadIdx.x;
    if (i >= total) return;
    float v = bias[i % NCOL];
#pragma unroll
    for (int s = 0; s < SLICES; s++) v += P[(size_t)s * total + i];
    if (ACT == 1) v = fmaxf(v, 0.0f);
    else v = 1.0f / (1.0f + expf(-v));
    out[i] = v;
}

// ---------------- multistage tf32 GEMM ----------------
// C[M,N] = A[M,K] @ W[K,N], 64x64 tile, 256 threads (8 warps 4x2),
// k-step 32, GSTAGES-deep cp.async pipeline.
// grid: x = n-tile, y = k-slice, z = m-tile.
// KSLICES>1: writes raw partials to C + ks*M*N (bias/act applied by epi_kernel).
// KSLICES==1: applies bias (if non-null) and ACT (0=none,1=relu,2=sigmoid).
template <int K, int N, int KSLICES, int ACT>
__global__ void __launch_bounds__(256) gemm_ms(
    const float* __restrict__ A, const float* __restrict__ W,
    const float* __restrict__ bias, float* __restrict__ C, int M) {
    constexpr int KSLICE = K / KSLICES;
    constexpr int KT = KSLICE / 32;

    extern __shared__ __align__(16) float smem[];
    float* AsBase = smem;                          // [GSTAGES][64][36]
    float* WsBase = smem + GSTAGES * 64 * 36;      // [GSTAGES][32][72]

    const int t = threadIdx.x;
    const int n0 = blockIdx.x * 64;
    const int ks = blockIdx.y;
    const int m0 = blockIdx.z * 64;
    const int kbase = ks * KSLICE;

    const int lane = t & 31, wid = t >> 5;
    const int g = lane >> 2, q = lane & 3;
    const int wm = (wid >> 1) << 4;   // 4 m-warps
    const int wn = (wid & 1) << 5;    // 2 n-warps

    auto As_ = [&](int s, int r, int c) -> float* { return AsBase + ((s * 64 + r) * 36 + c); };
    auto Ws_ = [&](int s, int r, int c) -> float* { return WsBase + ((s * 32 + r) * 72 + c); };

    auto load_stage = [&](int s, int kt) {
        if (kt < KT) {
            const int kk = kbase + kt * 32;
#pragma unroll
            for (int i = 0; i < 2; i++) {
                int id = t + i * 256;
                int r = id >> 3, c = id & 7;      // 64 rows x 8 chunks
                cp_async16(As_(s, r, c * 4), A + (size_t)(m0 + r) * K + kk + c * 4);
            }
#pragma unroll
            for (int i = 0; i < 2; i++) {
                int id = t + i * 256;
                int r = id >> 4, c = id & 15;     // 32 rows x 16 chunks
                cp_async16(Ws_(s, r, c * 4), W + (size_t)(kk + r) * N + n0 + c * 4);
            }
        }
        cp_commit();
    };

    // prologue: fill GSTAGES-1 stages
#pragma unroll
    for (int s = 0; s < GSTAGES - 1; s++) load_stage(s, s);

    float acc[4][4] = {};

    for (int kt = 0; kt < KT; kt++) {
        cp_wait<GSTAGES - 2>();
        __syncthreads();   // stage kt visible to all; all warps done with stage kt-1

        const int bb = kt & (GSTAGES - 1);
#pragma unroll
        for (int kk = 0; kk < 4; kk++) {
            const int k8 = kk * 8;
            uint32_t a0 = cvt_tf32(*As_(bb, wm + g, k8 + q));
            uint32_t a1 = cvt_tf32(*As_(bb, wm + g + 8, k8 + q));
            uint32_t a2 = cvt_tf32(*As_(bb, wm + g, k8 + q + 4));
            uint32_t a3 = cvt_tf32(*As_(bb, wm + g + 8, k8 + q + 4));
#pragma unroll
            for (int nf = 0; nf < 4; nf++) {
                uint32_t b0 = cvt_tf32(*Ws_(bb, k8 + q, wn + nf * 8 + g));
                uint32_t b1 = cvt_tf32(*Ws_(bb, k8 + q + 4, wn + nf * 8 + g));
                mma_tf32(acc[nf], a0, a1, a2, a3, b0, b1);
            }
        }
        // refill the stage computed at iter kt-1 (all warps past it per sync above)
        load_stage((kt + GSTAGES - 1) & (GSTAGES - 1), kt + GSTAGES - 1);
    }

    // epilogue
    float* Cout = C + (KSLICES > 1 ? (size_t)ks * M * N : 0);
#pragma unroll
    for (int nf = 0; nf < 4; nf++) {
#pragma unroll
        for (int i = 0; i < 4; i++) {
            int row = m0 + wm + g + ((i >> 1) << 3);
            int col = n0 + wn + nf * 8 + q * 2 + (i & 1);
            float v = acc[nf][i];
            if (KSLICES == 1) {
                if (bias) v += bias[col];
                if (ACT == 1) v = fmaxf(v, 0.0f);
                else if (ACT == 2) v = 1.0f / (1.0f + expf(-v));
            }
            Cout[(size_t)row * N + col] = v;
        }
    }
}

#define GEMM_SMEM (GSTAGES * (64 * 36 + 32 * 72) * (int)sizeof(float))  // 73728

// ---------------- launch ----------------
extern "C" void kernel_launch(void* const* d_in, const int* in_sizes, int n_in,
                              void* d_out, int out_size) {
    const float* x   = (const float*)d_in[0];
    const int*   ei  = (const int*)d_in[1];
    const float* Wg  = (const float*)d_in[2];
    const float* bg  = (const float*)d_in[3];
    const float* W1  = (const float*)d_in[4];
    const float* b1  = (const float*)d_in[5];
    const float* W2  = (const float*)d_in[6];
    const float* b2  = (const float*)d_in[7];
    float* out = (float*)d_out;

    const int* src = ei;
    const int* dst = ei + N_EDGES;

    float *H, *AGG, *DINV, *ZOUT, *Z2, *Z2P, *OUTP;
    int* DEG;
    cudaGetSymbolAddress((void**)&H, d_H);
    cudaGetSymbolAddress((void**)&AGG, d_AGG);
    cudaGetSymbolAddress((void**)&DEG, d_DEG);
    cudaGetSymbolAddress((void**)&DINV, d_DINV);
    cudaGetSymbolAddress((void**)&ZOUT, d_ZOUT);
    cudaGetSymbolAddress((void**)&Z2, d_Z2);
    cudaGetSymbolAddress((void**)&Z2P, d_Z2P);
    cudaGetSymbolAddress((void**)&OUTP, d_OUTP);

    // allow 72KB dynamic smem on the GEMM instantiations (host-side, capture-safe)
    cudaFuncSetAttribute((const void*)gemm_ms<TBL, LATENT, 1, 0>,
                         cudaFuncAttributeMaxDynamicSharedMemorySize, GEMM_SMEM);
    cudaFuncSetAttribute((const void*)gemm_ms<N2, HID, 4, 0>,
                         cudaFuncAttributeMaxDynamicSharedMemorySize, GEMM_SMEM);
    cudaFuncSetAttribute((const void*)gemm_ms<HID, N2, 8, 0>,
                         cudaFuncAttributeMaxDynamicSharedMemorySize, GEMM_SMEM);

    // 1. zero scratch accumulators
    zero_kernel<<<(N_NODES * LATENT + 255) / 256, 256>>>(AGG, DEG);

    // 2. in-degree + 3. dinv
    deg_kernel<<<(N_EDGES + 255) / 256, 256>>>(dst, DEG);
    dinv_kernel<<<(N_NODES + 255) / 256, 256>>>(DEG, DINV);

    // 4. h = x @ Wg   [5120,256]x[256,128]
    gemm_ms<TBL, LATENT, 1, 0><<<dim3(LATENT / 64, 1, N_NODES / 64), 256, GEMM_SMEM>>>(
        x, Wg, nullptr, H, N_NODES);

    // 5. scatter: agg[dst] += h[src] * norm
    scatter_kernel<<<N_EDGES / 8, 256>>>(H, src, dst, DINV, AGG);

    // 6. z = relu(agg + bg)
    relu_bias_kernel<<<(N_NODES * LATENT + 255) / 256, 256>>>(AGG, bg);

    // 7. per-graph outer products -> [64, 6400]
    outer_kernel<<<N_GRAPHS, 256>>>(AGG, ZOUT);

    // 8. z2 = relu(zout @ W1 + b1): split-K 4 -> 400 blocks, then reduce
    gemm_ms<N2, HID, 4, 0><<<dim3(HID / 64, 4, 1), 256, GEMM_SMEM>>>(
        ZOUT, W1, nullptr, Z2P, N_GRAPHS);
    epi_kernel<4, HID, 1><<<(N_GRAPHS * HID + 255) / 256, 256>>>(
        Z2P, b1, Z2, N_GRAPHS * HID);

    // 9. y = sigmoid(z2 @ W2 + b2): split-K 8 -> 400 blocks, then reduce
    gemm_ms<HID, N2, 8, 0><<<dim3(N2 / 64, 8, 1), 256, GEMM_SMEM>>>(
        Z2, W2, nullptr, OUTP, N_GRAPHS);
    epi_kernel<8, N2, 2><<<(N_GRAPHS * N2 + 255) / 256, 256>>>(
        OUTP, b2, out, N_GRAPHS * N2);
}

// round 6
// speedup vs baseline: 1.7225x; 1.0277x over previous
#include <cuda_runtime.h>
#include <cuda_bf16.h>
#include <cstdint>
#include <cstdio>

// ---------------- problem constants ----------------
#define N_NEURONS 80
#define TBL       256
#define LATENT    128
#define N_GRAPHS  64
#define N_NODES   (N_GRAPHS * N_NEURONS)   // 5120
#define N_EDGES   (N_NODES * 32)           // 163840
#define N2        (N_NEURONS * N_NEURONS)  // 6400
#define HID       (2 * N2)                 // 12800

#define GSTAGES 3
#define KS1 8     // split-K slices for GEMM1
#define KS2 16    // split-K slices for GEMM2

// ---------------- device scratch (no allocations allowed) ----------------
__device__ float d_H[N_NODES * LATENT];       // x @ Wg
__device__ float d_AGG[N_NODES * LATENT];     // scatter accumulation
__device__ int   d_DEG[N_NODES];
__device__ float d_DINV[N_NODES];
__device__ float d_ZOUT[N_GRAPHS * N2];       // outer products [64, 6400]
__device__ float d_Z2[N_GRAPHS * HID];        // hidden layer [64, 12800]
__device__ float d_Z2P[KS1 * N_GRAPHS * HID]; // GEMM1 split-K partials
__device__ float d_OUTP[KS2 * N_GRAPHS * N2]; // GEMM2 split-K partials

// ---------------- PTX helpers ----------------
__device__ __forceinline__ uint32_t cvt_tf32(float x) {
    uint32_t r;
    asm("cvt.rna.tf32.f32 %0, %1;" : "=r"(r) : "f"(x));
    return r;
}

__device__ __forceinline__ void mma_tf32(float c[4],
                                         uint32_t a0, uint32_t a1, uint32_t a2, uint32_t a3,
                                         uint32_t b0, uint32_t b1) {
    asm volatile(
        "mma.sync.aligned.m16n8k8.row.col.f32.tf32.tf32.f32 "
        "{%0,%1,%2,%3},{%4,%5,%6,%7},{%8,%9},{%0,%1,%2,%3};"
        : "+f"(c[0]), "+f"(c[1]), "+f"(c[2]), "+f"(c[3])
        : "r"(a0), "r"(a1), "r"(a2), "r"(a3), "r"(b0), "r"(b1));
}

__device__ __forceinline__ void cp_async16(void* smem_dst, const void* gmem_src) {
    uint32_t s = (uint32_t)__cvta_generic_to_shared(smem_dst);
    asm volatile("cp.async.cg.shared.global [%0], [%1], 16;" :: "r"(s), "l"(gmem_src));
}
__device__ __forceinline__ void cp_commit() { asm volatile("cp.async.commit_group;"); }
template <int NN>
__device__ __forceinline__ void cp_wait() { asm volatile("cp.async.wait_group %0;" :: "n"(NN)); }

// ---------------- small kernels ----------------
__global__ void zero_kernel(float* __restrict__ agg, int* __restrict__ deg) {
    int i = blockIdx.x * blockDim.x + threadIdx.x;
    if (i < N_NODES * LATENT) agg[i] = 0.0f;
    if (i < N_NODES) deg[i] = 0;
}

__global__ void deg_kernel(const int* __restrict__ dst, int* __restrict__ deg) {
    int i = blockIdx.x * blockDim.x + threadIdx.x;
    if (i < N_EDGES) atomicAdd(&deg[dst[i]], 1);
}

__global__ void dinv_kernel(const int* __restrict__ deg, float* __restrict__ dinv) {
    int i = blockIdx.x * blockDim.x + threadIdx.x;
    if (i < N_NODES) {
        int d = deg[i];
        dinv[i] = (d > 0) ? rsqrtf((float)d) : 0.0f;
    }
}

// one warp per edge: agg[dst] += h[src] * dinv[src]*dinv[dst]  (float4 per lane)
__global__ void __launch_bounds__(256) scatter_kernel(
    const float* __restrict__ H, const int* __restrict__ src, const int* __restrict__ dst,
    const float* __restrict__ dinv, float* __restrict__ agg) {
    int e = (blockIdx.x * blockDim.x + threadIdx.x) >> 5;
    int lane = threadIdx.x & 31;
    if (e >= N_EDGES) return;
    int s = src[e], d = dst[e];
    float nrm = dinv[s] * dinv[d];
    const float4* hp = reinterpret_cast<const float4*>(H + (size_t)s * LATENT);
    float4 v = hp[lane];
    v.x *= nrm; v.y *= nrm; v.z *= nrm; v.w *= nrm;
    float* ap = agg + (size_t)d * LATENT + lane * 4;
    asm volatile("red.global.add.v4.f32 [%0], {%1,%2,%3,%4};"
                 :: "l"(ap), "f"(v.x), "f"(v.y), "f"(v.z), "f"(v.w) : "memory");
}

__global__ void relu_bias_kernel(float* __restrict__ agg, const float* __restrict__ bg) {
    int i = blockIdx.x * blockDim.x + threadIdx.x;
    if (i < N_NODES * LATENT) {
        float v = agg[i] + bg[i & (LATENT - 1)];
        agg[i] = fmaxf(v, 0.0f);
    }
}

// per-graph z_b @ z_b^T : 64 blocks, 256 threads, 5x5 register tiles
__global__ void __launch_bounds__(256) outer_kernel(const float* __restrict__ Z,
                                                    float* __restrict__ Zo) {
    __shared__ float zs[N_NEURONS][LATENT + 1];
    int b = blockIdx.x;
    const float* zb = Z + (size_t)b * N_NEURONS * LATENT;
    for (int i = threadIdx.x; i < N_NEURONS * LATENT; i += 256) {
        zs[i >> 7][i & 127] = zb[i];
    }
    __syncthreads();
    int tx = threadIdx.x & 15, ty = threadIdx.x >> 4;
    int nB = ty * 5, mB = tx * 5;
    float acc[5][5] = {};
    for (int l = 0; l < LATENT; l++) {
        float zn[5], zm[5];
#pragma unroll
        for (int i = 0; i < 5; i++) { zn[i] = zs[nB + i][l]; zm[i] = zs[mB + i][l]; }
#pragma unroll
        for (int i = 0; i < 5; i++)
#pragma unroll
            for (int j = 0; j < 5; j++) acc[i][j] = fmaf(zn[i], zm[j], acc[i][j]);
    }
    float* ob = Zo + (size_t)b * N2;
#pragma unroll
    for (int i = 0; i < 5; i++)
#pragma unroll
        for (int j = 0; j < 5; j++)
            ob[(nB + i) * N_NEURONS + mB + j] = acc[i][j];
}

// split-K reduction epilogue: out = act(sum_s P[s] + bias[col])
template <int SLICES, int NCOL, int ACT>
__global__ void epi_kernel(const float* __restrict__ P, const float* __restrict__ bias,
                           float* __restrict__ out, int total) {
    int i = blockIdx.x * blockDim.x + threadIdx.x;
    if (i >= total) return;
    float v = bias[i % NCOL];
#pragma unroll
    for (int s = 0; s < SLICES; s++) v += P[(size_t)s * total + i];
    if (ACT == 1) v = fmaxf(v, 0.0f);
    else v = 1.0f / (1.0f + expf(-v));
    out[i] = v;
}

// ---------------- multistage tf32 GEMM ----------------
// C[M,N] = A[M,K] @ W[K,N], 64x64 tile, 256 threads (8 warps 4x2),
// k-step 32, GSTAGES-deep cp.async pipeline, loads issued BEFORE compute.
// grid: x = n-tile, y = k-slice, z = m-tile.
// KSLICES>1: writes raw partials to C + ks*M*N (bias/act applied by epi_kernel).
template <int K, int N, int KSLICES, int ACT>
__global__ void __launch_bounds__(256) gemm_ms(
    const float* __restrict__ A, const float* __restrict__ W,
    const float* __restrict__ bias, float* __restrict__ C, int M) {
    constexpr int KSLICE = K / KSLICES;
    constexpr int KT = KSLICE / 32;

    extern __shared__ __align__(16) float smem[];
    float* AsBase = smem;                          // [GSTAGES][64][36]
    float* WsBase = smem + GSTAGES * 64 * 36;      // [GSTAGES][32][72]

    const int t = threadIdx.x;
    const int n0 = blockIdx.x * 64;
    const int ks = blockIdx.y;
    const int m0 = blockIdx.z * 64;
    const int kbase = ks * KSLICE;

    const int lane = t & 31, wid = t >> 5;
    const int g = lane >> 2, q = lane & 3;
    const int wm = (wid >> 1) << 4;   // 4 m-warps
    const int wn = (wid & 1) << 5;    // 2 n-warps

    auto As_ = [&](int s, int r, int c) -> float* { return AsBase + ((s * 64 + r) * 36 + c); };
    auto Ws_ = [&](int s, int r, int c) -> float* { return WsBase + ((s * 32 + r) * 72 + c); };

    auto load_stage = [&](int s, int kt) {
        if (kt < KT) {
            const int kk = kbase + kt * 32;
#pragma unroll
            for (int i = 0; i < 2; i++) {
                int id = t + i * 256;
                int r = id >> 3, c = id & 7;      // 64 rows x 8 chunks
                cp_async16(As_(s, r, c * 4), A + (size_t)(m0 + r) * K + kk + c * 4);
            }
#pragma unroll
            for (int i = 0; i < 2; i++) {
                int id = t + i * 256;
                int r = id >> 4, c = id & 15;     // 32 rows x 16 chunks
                cp_async16(Ws_(s, r, c * 4), W + (size_t)(kk + r) * N + n0 + c * 4);
            }
        }
        cp_commit();
    };

    // prologue: fill GSTAGES-1 stages
#pragma unroll
    for (int s = 0; s < GSTAGES - 1; s++) load_stage(s, s);

    float acc[4][4] = {};

    int sidx = 0;                 // stage holding iteration kt's tiles
    for (int kt = 0; kt < KT; kt++) {
        cp_wait<GSTAGES - 2>();
        __syncthreads();   // stage kt ready; every warp done reading stage (kt-1)

        // refill freed stage FIRST, so loads are in flight during compute
        int fill = sidx + (GSTAGES - 1);
        if (fill >= GSTAGES) fill -= GSTAGES;
        load_stage(fill, kt + GSTAGES - 1);

        const int bb = sidx;
#pragma unroll
        for (int kk = 0; kk < 4; kk++) {
            const int k8 = kk * 8;
            uint32_t a0 = cvt_tf32(*As_(bb, wm + g, k8 + q));
            uint32_t a1 = cvt_tf32(*As_(bb, wm + g + 8, k8 + q));
            uint32_t a2 = cvt_tf32(*As_(bb, wm + g, k8 + q + 4));
            uint32_t a3 = cvt_tf32(*As_(bb, wm + g + 8, k8 + q + 4));
#pragma unroll
            for (int nf = 0; nf < 4; nf++) {
                uint32_t b0 = cvt_tf32(*Ws_(bb, k8 + q, wn + nf * 8 + g));
                uint32_t b1 = cvt_tf32(*Ws_(bb, k8 + q + 4, wn + nf * 8 + g));
                mma_tf32(acc[nf], a0, a1, a2, a3, b0, b1);
            }
        }
        sidx = sidx + 1 == GSTAGES ? 0 : sidx + 1;
    }

    // epilogue
    float* Cout = C + (KSLICES > 1 ? (size_t)ks * M * N : 0);
#pragma unroll
    for (int nf = 0; nf < 4; nf++) {
#pragma unroll
        for (int i = 0; i < 4; i++) {
            int row = m0 + wm + g + ((i >> 1) << 3);
            int col = n0 + wn + nf * 8 + q * 2 + (i & 1);
            float v = acc[nf][i];
            if (KSLICES == 1) {
                if (bias) v += bias[col];
                if (ACT == 1) v = fmaxf(v, 0.0f);
                else if (ACT == 2) v = 1.0f / (1.0f + expf(-v));
            }
            Cout[(size_t)row * N + col] = v;
        }
    }
}

#define GEMM_SMEM (GSTAGES * (64 * 36 + 32 * 72) * (int)sizeof(float))  // 55296

// ---------------- launch ----------------
extern "C" void kernel_launch(void* const* d_in, const int* in_sizes, int n_in,
                              void* d_out, int out_size) {
    const float* x   = (const float*)d_in[0];
    const int*   ei  = (const int*)d_in[1];
    const float* Wg  = (const float*)d_in[2];
    const float* bg  = (const float*)d_in[3];
    const float* W1  = (const float*)d_in[4];
    const float* b1  = (const float*)d_in[5];
    const float* W2  = (const float*)d_in[6];
    const float* b2  = (const float*)d_in[7];
    float* out = (float*)d_out;

    const int* src = ei;
    const int* dst = ei + N_EDGES;

    float *H, *AGG, *DINV, *ZOUT, *Z2, *Z2P, *OUTP;
    int* DEG;
    cudaGetSymbolAddress((void**)&H, d_H);
    cudaGetSymbolAddress((void**)&AGG, d_AGG);
    cudaGetSymbolAddress((void**)&DEG, d_DEG);
    cudaGetSymbolAddress((void**)&DINV, d_DINV);
    cudaGetSymbolAddress((void**)&ZOUT, d_ZOUT);
    cudaGetSymbolAddress((void**)&Z2, d_Z2);
    cudaGetSymbolAddress((void**)&Z2P, d_Z2P);
    cudaGetSymbolAddress((void**)&OUTP, d_OUTP);

    cudaFuncSetAttribute((const void*)gemm_ms<TBL, LATENT, 1, 0>,
                         cudaFuncAttributeMaxDynamicSharedMemorySize, GEMM_SMEM);
    cudaFuncSetAttribute((const void*)gemm_ms<N2, HID, KS1, 0>,
                         cudaFuncAttributeMaxDynamicSharedMemorySize, GEMM_SMEM);
    cudaFuncSetAttribute((const void*)gemm_ms<HID, N2, KS2, 0>,
                         cudaFuncAttributeMaxDynamicSharedMemorySize, GEMM_SMEM);

    // 1. zero scratch accumulators
    zero_kernel<<<(N_NODES * LATENT + 255) / 256, 256>>>(AGG, DEG);

    // 2. in-degree + 3. dinv
    deg_kernel<<<(N_EDGES + 255) / 256, 256>>>(dst, DEG);
    dinv_kernel<<<(N_NODES + 255) / 256, 256>>>(DEG, DINV);

    // 4. h = x @ Wg   [5120,256]x[256,128]
    gemm_ms<TBL, LATENT, 1, 0><<<dim3(LATENT / 64, 1, N_NODES / 64), 256, GEMM_SMEM>>>(
        x, Wg, nullptr, H, N_NODES);

    // 5. scatter: agg[dst] += h[src] * norm
    scatter_kernel<<<N_EDGES / 8, 256>>>(H, src, dst, DINV, AGG);

    // 6. z = relu(agg + bg)
    relu_bias_kernel<<<(N_NODES * LATENT + 255) / 256, 256>>>(AGG, bg);

    // 7. per-graph outer products -> [64, 6400]
    outer_kernel<<<N_GRAPHS, 256>>>(AGG, ZOUT);

    // 8. z2 = relu(zout @ W1 + b1): split-K 8 -> 1600 blocks, then reduce
    gemm_ms<N2, HID, KS1, 0><<<dim3(HID / 64, KS1, 1), 256, GEMM_SMEM>>>(
        ZOUT, W1, nullptr, Z2P, N_GRAPHS);
    epi_kernel<KS1, HID, 1><<<(N_GRAPHS * HID + 255) / 256, 256>>>(
        Z2P, b1, Z2, N_GRAPHS * HID);

    // 9. y = sigmoid(z2 @ W2 + b2): split-K 16 -> 1600 blocks, then reduce
    gemm_ms<HID, N2, KS2, 0><<<dim3(N2 / 64, KS2, 1), 256, GEMM_SMEM>>>(
        Z2, W2, nullptr, OUTP, N_GRAPHS);
    epi_kernel<KS2, N2, 2><<<(N_GRAPHS * N2 + 255) / 256, 256>>>(
        OUTP, b2, out, N_GRAPHS * N2);
}

// round 7
// speedup vs baseline: 1.8110x; 1.0514x over previous
#include <cuda_runtime.h>
#include <cuda_bf16.h>
#include <cstdint>
#include <cstdio>

// ---------------- problem constants ----------------
#define N_NEURONS 80
#define TBL       256
#define LATENT    128
#define N_GRAPHS  64
#define N_NODES   (N_GRAPHS * N_NEURONS)   // 5120
#define N_EDGES   (N_NODES * 32)           // 163840
#define N2        (N_NEURONS * N_NEURONS)  // 6400
#define HID       (2 * N2)                 // 12800

#define GSTAGES 3
#define KS1 10    // split-K slices for GEMM1 (KSLICE=640, KT=20)
#define KS2 20    // split-K slices for GEMM2 (KSLICE=640, KT=20)

// ---------------- device scratch (no allocations allowed) ----------------
__device__ float d_H[N_NODES * LATENT];       // x @ Wg
__device__ float d_AGG[N_NODES * LATENT];     // scatter accumulation
__device__ int   d_DEG[N_NODES];
__device__ float d_DINV[N_NODES];
__device__ float d_ZOUT[N_GRAPHS * N2];       // outer products [64, 6400]
__device__ float d_Z2[N_GRAPHS * HID];        // hidden layer [64, 12800]
__device__ float d_Z2P[KS1 * N_GRAPHS * HID]; // GEMM1 split-K partials (32.8MB)
__device__ float d_OUTP[KS2 * N_GRAPHS * N2]; // GEMM2 split-K partials (32.8MB)

// ---------------- PTX helpers ----------------
__device__ __forceinline__ uint32_t cvt_tf32(float x) {
    uint32_t r;
    asm("cvt.rna.tf32.f32 %0, %1;" : "=r"(r) : "f"(x));
    return r;
}

__device__ __forceinline__ void mma_tf32(float c[4],
                                         uint32_t a0, uint32_t a1, uint32_t a2, uint32_t a3,
                                         uint32_t b0, uint32_t b1) {
    asm volatile(
        "mma.sync.aligned.m16n8k8.row.col.f32.tf32.tf32.f32 "
        "{%0,%1,%2,%3},{%4,%5,%6,%7},{%8,%9},{%0,%1,%2,%3};"
        : "+f"(c[0]), "+f"(c[1]), "+f"(c[2]), "+f"(c[3])
        : "r"(a0), "r"(a1), "r"(a2), "r"(a3), "r"(b0), "r"(b1));
}

__device__ __forceinline__ void cp_async16(void* smem_dst, const void* gmem_src) {
    uint32_t s = (uint32_t)__cvta_generic_to_shared(smem_dst);
    asm volatile("cp.async.cg.shared.global [%0], [%1], 16;" :: "r"(s), "l"(gmem_src));
}
__device__ __forceinline__ void cp_commit() { asm volatile("cp.async.commit_group;"); }
template <int NN>
__device__ __forceinline__ void cp_wait() { asm volatile("cp.async.wait_group %0;" :: "n"(NN)); }

// ---------------- small kernels ----------------
__global__ void zero_kernel(float* __restrict__ agg, int* __restrict__ deg) {
    int i = blockIdx.x * blockDim.x + threadIdx.x;
    if (i < N_NODES * LATENT) agg[i] = 0.0f;
    if (i < N_NODES) deg[i] = 0;
}

__global__ void deg_kernel(const int* __restrict__ dst, int* __restrict__ deg) {
    int i = blockIdx.x * blockDim.x + threadIdx.x;
    if (i < N_EDGES) atomicAdd(&deg[dst[i]], 1);
}

__global__ void dinv_kernel(const int* __restrict__ deg, float* __restrict__ dinv) {
    int i = blockIdx.x * blockDim.x + threadIdx.x;
    if (i < N_NODES) {
        int d = deg[i];
        dinv[i] = (d > 0) ? rsqrtf((float)d) : 0.0f;
    }
}

// one warp per edge: agg[dst] += h[src] * dinv[src]*dinv[dst]  (float4 per lane)
__global__ void __launch_bounds__(256) scatter_kernel(
    const float* __restrict__ H, const int* __restrict__ src, const int* __restrict__ dst,
    const float* __restrict__ dinv, float* __restrict__ agg) {
    int e = (blockIdx.x * blockDim.x + threadIdx.x) >> 5;
    int lane = threadIdx.x & 31;
    if (e >= N_EDGES) return;
    int s = src[e], d = dst[e];
    float nrm = dinv[s] * dinv[d];
    const float4* hp = reinterpret_cast<const float4*>(H + (size_t)s * LATENT);
    float4 v = hp[lane];
    v.x *= nrm; v.y *= nrm; v.z *= nrm; v.w *= nrm;
    float* ap = agg + (size_t)d * LATENT + lane * 4;
    asm volatile("red.global.add.v4.f32 [%0], {%1,%2,%3,%4};"
                 :: "l"(ap), "f"(v.x), "f"(v.y), "f"(v.z), "f"(v.w) : "memory");
}

__global__ void relu_bias_kernel(float* __restrict__ agg, const float* __restrict__ bg) {
    int i = blockIdx.x * blockDim.x + threadIdx.x;
    if (i < N_NODES * LATENT) {
        float v = agg[i] + bg[i & (LATENT - 1)];
        agg[i] = fmaxf(v, 0.0f);
    }
}

// per-graph z_b @ z_b^T : 64 blocks, 256 threads, 5x5 register tiles
__global__ void __launch_bounds__(256) outer_kernel(const float* __restrict__ Z,
                                                    float* __restrict__ Zo) {
    __shared__ float zs[N_NEURONS][LATENT + 1];
    int b = blockIdx.x;
    const float* zb = Z + (size_t)b * N_NEURONS * LATENT;
    for (int i = threadIdx.x; i < N_NEURONS * LATENT; i += 256) {
        zs[i >> 7][i & 127] = zb[i];
    }
    __syncthreads();
    int tx = threadIdx.x & 15, ty = threadIdx.x >> 4;
    int nB = ty * 5, mB = tx * 5;
    float acc[5][5] = {};
    for (int l = 0; l < LATENT; l++) {
        float zn[5], zm[5];
#pragma unroll
        for (int i = 0; i < 5; i++) { zn[i] = zs[nB + i][l]; zm[i] = zs[mB + i][l]; }
#pragma unroll
        for (int i = 0; i < 5; i++)
#pragma unroll
            for (int j = 0; j < 5; j++) acc[i][j] = fmaf(zn[i], zm[j], acc[i][j]);
    }
    float* ob = Zo + (size_t)b * N2;
#pragma unroll
    for (int i = 0; i < 5; i++)
#pragma unroll
        for (int j = 0; j < 5; j++)
            ob[(nB + i) * N_NEURONS + mB + j] = acc[i][j];
}

// split-K reduction epilogue: out = act(sum_s P[s] + bias[col])
template <int SLICES, int NCOL, int ACT>
__global__ void epi_kernel(const float* __restrict__ P, const float* __restrict__ bias,
                           float* __restrict__ out, int total) {
    int i = blockIdx.x * blockDim.x + threadIdx.x;
    if (i >= total) return;
    float v = bias[i % NCOL];
#pragma unroll
    for (int s = 0; s < SLICES; s++) v += P[(size_t)s * total + i];
    if (ACT == 1) v = fmaxf(v, 0.0f);
    else v = 1.0f / (1.0f + expf(-v));
    out[i] = v;
}

// ---------------- GCN GEMM (64x64 tile, as before) ----------------
template <int K, int N>
__global__ void __launch_bounds__(256) gemm_ms(
    const float* __restrict__ A, const float* __restrict__ W,
    float* __restrict__ C) {
    constexpr int KT = K / 32;

    extern __shared__ __align__(16) float smem[];
    float* AsBase = smem;                          // [GSTAGES][64][36]
    float* WsBase = smem + GSTAGES * 64 * 36;      // [GSTAGES][32][72]

    const int t = threadIdx.x;
    const int n0 = blockIdx.x * 64;
    const int m0 = blockIdx.z * 64;

    const int lane = t & 31, wid = t >> 5;
    const int g = lane >> 2, q = lane & 3;
    const int wm = (wid >> 1) << 4;
    const int wn = (wid & 1) << 5;

    auto As_ = [&](int s, int r, int c) -> float* { return AsBase + ((s * 64 + r) * 36 + c); };
    auto Ws_ = [&](int s, int r, int c) -> float* { return WsBase + ((s * 32 + r) * 72 + c); };

    auto load_stage = [&](int s, int kt) {
        if (kt < KT) {
            const int kk = kt * 32;
#pragma unroll
            for (int i = 0; i < 2; i++) {
                int id = t + i * 256;
                int r = id >> 3, c = id & 7;
                cp_async16(As_(s, r, c * 4), A + (size_t)(m0 + r) * K + kk + c * 4);
            }
#pragma unroll
            for (int i = 0; i < 2; i++) {
                int id = t + i * 256;
                int r = id >> 4, c = id & 15;
                cp_async16(Ws_(s, r, c * 4), W + (size_t)(kk + r) * N + n0 + c * 4);
            }
        }
        cp_commit();
    };

#pragma unroll
    for (int s = 0; s < GSTAGES - 1; s++) load_stage(s, s);

    float acc[4][4] = {};
    int sidx = 0;
    for (int kt = 0; kt < KT; kt++) {
        cp_wait<GSTAGES - 2>();
        __syncthreads();
        int fill = sidx + (GSTAGES - 1);
        if (fill >= GSTAGES) fill -= GSTAGES;
        load_stage(fill, kt + GSTAGES - 1);

        const int bb = sidx;
#pragma unroll
        for (int kk = 0; kk < 4; kk++) {
            const int k8 = kk * 8;
            uint32_t a0 = cvt_tf32(*As_(bb, wm + g, k8 + q));
            uint32_t a1 = cvt_tf32(*As_(bb, wm + g + 8, k8 + q));
            uint32_t a2 = cvt_tf32(*As_(bb, wm + g, k8 + q + 4));
            uint32_t a3 = cvt_tf32(*As_(bb, wm + g + 8, k8 + q + 4));
#pragma unroll
            for (int nf = 0; nf < 4; nf++) {
                uint32_t b0 = cvt_tf32(*Ws_(bb, k8 + q, wn + nf * 8 + g));
                uint32_t b1 = cvt_tf32(*Ws_(bb, k8 + q + 4, wn + nf * 8 + g));
                mma_tf32(acc[nf], a0, a1, a2, a3, b0, b1);
            }
        }
        sidx = sidx + 1 == GSTAGES ? 0 : sidx + 1;
    }

#pragma unroll
    for (int nf = 0; nf < 4; nf++) {
#pragma unroll
        for (int i = 0; i < 4; i++) {
            int row = m0 + wm + g + ((i >> 1) << 3);
            int col = n0 + wn + nf * 8 + q * 2 + (i & 1);
            C[(size_t)row * N + col] = acc[nf][i];
        }
    }
}

// ---------------- big GEMM: 64x128 tile, XOR-swizzled W, split-K ----------------
// C[64,N] partials: P[ks][64][N]. 256 threads = 8 warps (4 m x 2 n), warp tile 16x64.
// W smem tile [32][128], col-swizzled: float col' = col ^ ((row&3)<<3) (16B-chunk safe).
template <int K, int N, int KSLICES>
__global__ void __launch_bounds__(256, 3) gemm_big(
    const float* __restrict__ A, const float* __restrict__ W,
    float* __restrict__ P) {
    constexpr int KSLICE = K / KSLICES;
    constexpr int KT = KSLICE / 32;

    extern __shared__ __align__(16) float smem[];
    float* AsBase = smem;                          // [GSTAGES][64][36]
    float* WsBase = smem + GSTAGES * 64 * 36;      // [GSTAGES][32][128] swizzled

    const int t = threadIdx.x;
    const int n0 = blockIdx.x * 128;
    const int ks = blockIdx.y;
    const int kbase = ks * KSLICE;

    const int lane = t & 31, wid = t >> 5;
    const int g = lane >> 2, q = lane & 3;
    const int wm = (wid >> 1) << 4;   // 4 m-warps: rows 0,16,32,48
    const int wn = (wid & 1) << 6;    // 2 n-warps: cols 0,64

    auto As_ = [&](int s, int r, int c) -> float* { return AsBase + ((s * 64 + r) * 36 + c); };
    auto Ws_ = [&](int s, int r, int c) -> float* { return WsBase + ((s * 32 + r) * 128 + c); };

    auto load_stage = [&](int s, int kt) {
        if (kt < KT) {
            const int kk = kbase + kt * 32;
            // A: 64x32 = 512 chunks
#pragma unroll
            for (int i = 0; i < 2; i++) {
                int id = t + i * 256;
                int r = id >> 3, c = id & 7;
                cp_async16(As_(s, r, c * 4), A + (size_t)r * K + kk + c * 4);
            }
            // W: 32x128 = 1024 chunks, swizzle chunk: c4 ^ ((r&3)<<1)
#pragma unroll
            for (int i = 0; i < 4; i++) {
                int id = t + i * 256;
                int r = id >> 5, c4 = id & 31;
                int sc4 = c4 ^ ((r & 3) << 1);
                cp_async16(Ws_(s, r, sc4 * 4), W + (size_t)(kk + r) * N + n0 + c4 * 4);
            }
        }
        cp_commit();
    };

#pragma unroll
    for (int s = 0; s < GSTAGES - 1; s++) load_stage(s, s);

    float acc[8][4] = {};
    int sidx = 0;
    for (int kt = 0; kt < KT; kt++) {
        cp_wait<GSTAGES - 2>();
        __syncthreads();
        int fill = sidx + (GSTAGES - 1);
        if (fill >= GSTAGES) fill -= GSTAGES;
        load_stage(fill, kt + GSTAGES - 1);

        const int bb = sidx;
        const int sw = q << 3;   // swizzle for both row q and row q+4 ((q+4)&3 == q)
#pragma unroll
        for (int kk = 0; kk < 4; kk++) {
            const int k8 = kk * 8;
            uint32_t a0 = cvt_tf32(*As_(bb, wm + g, k8 + q));
            uint32_t a1 = cvt_tf32(*As_(bb, wm + g + 8, k8 + q));
            uint32_t a2 = cvt_tf32(*As_(bb, wm + g, k8 + q + 4));
            uint32_t a3 = cvt_tf32(*As_(bb, wm + g + 8, k8 + q + 4));
#pragma unroll
            for (int nf = 0; nf < 8; nf++) {
                int col = (wn + nf * 8 + g) ^ sw;
                uint32_t b0 = cvt_tf32(*Ws_(bb, k8 + q, col));
                uint32_t b1 = cvt_tf32(*Ws_(bb, k8 + q + 4, col));
                mma_tf32(acc[nf], a0, a1, a2, a3, b0, b1);
            }
        }
        sidx = sidx + 1 == GSTAGES ? 0 : sidx + 1;
    }

    float* Pout = P + (size_t)ks * 64 * N;
#pragma unroll
    for (int nf = 0; nf < 8; nf++) {
#pragma unroll
        for (int i = 0; i < 4; i++) {
            int row = wm + g + ((i >> 1) << 3);
            int col = n0 + wn + nf * 8 + q * 2 + (i & 1);
            Pout[(size_t)row * N + col] = acc[nf][i];
        }
    }
}

#define GEMM_SMEM (GSTAGES * (64 * 36 + 32 * 72) * (int)sizeof(float))    // 55296
#define BIG_SMEM  (GSTAGES * (64 * 36 + 32 * 128) * (int)sizeof(float))   // 76800

// ---------------- launch ----------------
extern "C" void kernel_launch(void* const* d_in, const int* in_sizes, int n_in,
                              void* d_out, int out_size) {
    const float* x   = (const float*)d_in[0];
    const int*   ei  = (const int*)d_in[1];
    const float* Wg  = (const float*)d_in[2];
    const float* bg  = (const float*)d_in[3];
    const float* W1  = (const float*)d_in[4];
    const float* b1  = (const float*)d_in[5];
    const float* W2  = (const float*)d_in[6];
    const float* b2  = (const float*)d_in[7];
    float* out = (float*)d_out;

    const int* src = ei;
    const int* dst = ei + N_EDGES;

    float *H, *AGG, *DINV, *ZOUT, *Z2, *Z2P, *OUTP;
    int* DEG;
    cudaGetSymbolAddress((void**)&H, d_H);
    cudaGetSymbolAddress((void**)&AGG, d_AGG);
    cudaGetSymbolAddress((void**)&DEG, d_DEG);
    cudaGetSymbolAddress((void**)&DINV, d_DINV);
    cudaGetSymbolAddress((void**)&ZOUT, d_ZOUT);
    cudaGetSymbolAddress((void**)&Z2, d_Z2);
    cudaGetSymbolAddress((void**)&Z2P, d_Z2P);
    cudaGetSymbolAddress((void**)&OUTP, d_OUTP);

    cudaFuncSetAttribute((const void*)gemm_ms<TBL, LATENT>,
                         cudaFuncAttributeMaxDynamicSharedMemorySize, GEMM_SMEM);
    cudaFuncSetAttribute((const void*)gemm_big<N2, HID, KS1>,
                         cudaFuncAttributeMaxDynamicSharedMemorySize, BIG_SMEM);
    cudaFuncSetAttribute((const void*)gemm_big<HID, N2, KS2>,
                         cudaFuncAttributeMaxDynamicSharedMemorySize, BIG_SMEM);

    // 1. zero scratch accumulators
    zero_kernel<<<(N_NODES * LATENT + 255) / 256, 256>>>(AGG, DEG);

    // 2. in-degree + 3. dinv
    deg_kernel<<<(N_EDGES + 255) / 256, 256>>>(dst, DEG);
    dinv_kernel<<<(N_NODES + 255) / 256, 256>>>(DEG, DINV);

    // 4. h = x @ Wg   [5120,256]x[256,128]
    gemm_ms<TBL, LATENT><<<dim3(LATENT / 64, 1, N_NODES / 64), 256, GEMM_SMEM>>>(x, Wg, H);

    // 5. scatter: agg[dst] += h[src] * norm
    scatter_kernel<<<N_EDGES / 8, 256>>>(H, src, dst, DINV, AGG);

    // 6. z = relu(agg + bg)
    relu_bias_kernel<<<(N_NODES * LATENT + 255) / 256, 256>>>(AGG, bg);

    // 7. per-graph outer products -> [64, 6400]
    outer_kernel<<<N_GRAPHS, 256>>>(AGG, ZOUT);

    // 8. z2 = relu(zout @ W1 + b1): 100 n-tiles x 10 k-slices = 1000 blocks
    gemm_big<N2, HID, KS1><<<dim3(HID / 128, KS1, 1), 256, BIG_SMEM>>>(ZOUT, W1, Z2P);
    epi_kernel<KS1, HID, 1><<<(N_GRAPHS * HID + 255) / 256, 256>>>(
        Z2P, b1, Z2, N_GRAPHS * HID);

    // 9. y = sigmoid(z2 @ W2 + b2): 50 n-tiles x 20 k-slices = 1000 blocks
    gemm_big<HID, N2, KS2><<<dim3(N2 / 128, KS2, 1), 256, BIG_SMEM>>>(Z2, W2, OUTP);
    epi_kernel<KS2, N2, 2><<<(N_GRAPHS * N2 + 255) / 256, 256>>>(
        OUTP, b2, out, N_GRAPHS * N2);
}

// round 12
// speedup vs baseline: 1.9578x; 1.0811x over previous
#include <cuda_runtime.h>
#include <cuda_bf16.h>
#include <cstdint>
#include <cstdio>

// ---------------- problem constants ----------------
#define N_NEURONS 80
#define TBL       256
#define LATENT    128
#define N_GRAPHS  64
#define N_NODES   (N_GRAPHS * N_NEURONS)   // 5120
#define N_EDGES   (N_NODES * 32)           // 163840
#define N2        (N_NEURONS * N_NEURONS)  // 6400
#define HID       (2 * N2)                 // 12800

#define GSTAGES 3     // GCN gemm stages
#define WSTAGES 3     // big gemm stages
#define KS1 8         // split-K GEMM1: KSLICE=800, KT=25, 100x8=800 blocks
#define KS2 16        // split-K GEMM2: KSLICE=800, KT=25, 50x16=800 blocks

// ---------------- device scratch ----------------
__device__ float d_H[N_NODES * LATENT];
__device__ float d_AGG[N_NODES * LATENT];
__device__ int   d_DEG[N_NODES];
__device__ float d_DINV[N_NODES];
__device__ float d_ZOUT[N_GRAPHS * N2];       // [64][6400], tf32-rounded
__device__ float d_Z2[N_GRAPHS * HID];        // [64][12800], tf32-rounded
__device__ float d_Z2P[KS1 * HID * N_GRAPHS]; // partials [ks][nout][64]
__device__ float d_OUTP[KS2 * N2 * N_GRAPHS]; // partials [ks][nout][64]

// ---------------- PTX helpers ----------------
__device__ __forceinline__ uint32_t cvt_tf32(float x) {
    uint32_t r;
    asm("cvt.rna.tf32.f32 %0, %1;" : "=r"(r) : "f"(x));
    return r;
}

__device__ __forceinline__ void mma_tf32(float c[4],
                                         uint32_t a0, uint32_t a1, uint32_t a2, uint32_t a3,
                                         uint32_t b0, uint32_t b1) {
    asm volatile(
        "mma.sync.aligned.m16n8k8.row.col.f32.tf32.tf32.f32 "
        "{%0,%1,%2,%3},{%4,%5,%6,%7},{%8,%9},{%0,%1,%2,%3};"
        : "+f"(c[0]), "+f"(c[1]), "+f"(c[2]), "+f"(c[3])
        : "r"(a0), "r"(a1), "r"(a2), "r"(a3), "r"(b0), "r"(b1));
}

__device__ __forceinline__ void cp_async16(void* smem_dst, const void* gmem_src) {
    uint32_t s = (uint32_t)__cvta_generic_to_shared(smem_dst);
    asm volatile("cp.async.cg.shared.global [%0], [%1], 16;" :: "r"(s), "l"(gmem_src));
}
__device__ __forceinline__ void cp_commit() { asm volatile("cp.async.commit_group;"); }
template <int NN>
__device__ __forceinline__ void cp_wait() { asm volatile("cp.async.wait_group %0;" :: "n"(NN)); }

// ---------------- small kernels ----------------
__global__ void zero_kernel(float* __restrict__ agg, int* __restrict__ deg) {
    int i = blockIdx.x * blockDim.x + threadIdx.x;
    if (i < N_NODES * LATENT) agg[i] = 0.0f;
    if (i < N_NODES) deg[i] = 0;
}

__global__ void deg_kernel(const int* __restrict__ dst, int* __restrict__ deg) {
    int i = blockIdx.x * blockDim.x + threadIdx.x;
    if (i < N_EDGES) atomicAdd(&deg[dst[i]], 1);
}

__global__ void dinv_kernel(const int* __restrict__ deg, float* __restrict__ dinv) {
    int i = blockIdx.x * blockDim.x + threadIdx.x;
    if (i < N_NODES) {
        int d = deg[i];
        dinv[i] = (d > 0) ? rsqrtf((float)d) : 0.0f;
    }
}

__global__ void __launch_bounds__(256) scatter_kernel(
    const float* __restrict__ H, const int* __restrict__ src, const int* __restrict__ dst,
    const float* __restrict__ dinv, float* __restrict__ agg) {
    int e = (blockIdx.x * blockDim.x + threadIdx.x) >> 5;
    int lane = threadIdx.x & 31;
    if (e >= N_EDGES) return;
    int s = src[e], d = dst[e];
    float nrm = dinv[s] * dinv[d];
    const float4* hp = reinterpret_cast<const float4*>(H + (size_t)s * LATENT);
    float4 v = hp[lane];
    v.x *= nrm; v.y *= nrm; v.z *= nrm; v.w *= nrm;
    float* ap = agg + (size_t)d * LATENT + lane * 4;
    asm volatile("red.global.add.v4.f32 [%0], {%1,%2,%3,%4};"
                 :: "l"(ap), "f"(v.x), "f"(v.y), "f"(v.z), "f"(v.w) : "memory");
}

__global__ void relu_bias_kernel(float* __restrict__ agg, const float* __restrict__ bg) {
    int i = blockIdx.x * blockDim.x + threadIdx.x;
    if (i < N_NODES * LATENT) {
        float v = agg[i] + bg[i & (LATENT - 1)];
        agg[i] = fmaxf(v, 0.0f);
    }
}

// per-graph z zT; output tf32-rounded so big-GEMM B-side reads are cvt-free
__global__ void __launch_bounds__(256) outer_kernel(const float* __restrict__ Z,
                                                    float* __restrict__ Zo) {
    __shared__ float zs[N_NEURONS][LATENT + 1];
    int b = blockIdx.x;
    const float* zb = Z + (size_t)b * N_NEURONS * LATENT;
    for (int i = threadIdx.x; i < N_NEURONS * LATENT; i += 256) {
        zs[i >> 7][i & 127] = zb[i];
    }
    __syncthreads();
    int tx = threadIdx.x & 15, ty = threadIdx.x >> 4;
    int nB = ty * 5, mB = tx * 5;
    float acc[5][5] = {};
    for (int l = 0; l < LATENT; l++) {
        float zn[5], zm[5];
#pragma unroll
        for (int i = 0; i < 5; i++) { zn[i] = zs[nB + i][l]; zm[i] = zs[mB + i][l]; }
#pragma unroll
        for (int i = 0; i < 5; i++)
#pragma unroll
            for (int j = 0; j < 5; j++) acc[i][j] = fmaf(zn[i], zm[j], acc[i][j]);
    }
    float* ob = Zo + (size_t)b * N2;
#pragma unroll
    for (int i = 0; i < 5; i++)
#pragma unroll
        for (int j = 0; j < 5; j++)
            ob[(nB + i) * N_NEURONS + mB + j] = __uint_as_float(cvt_tf32(acc[i][j]));
}

// split-K reduce over transposed partials P[s][nout][64].
// ACT==1: relu + tf32-round, write Z2[b][NCOLK] (transpose). ACT==2: sigmoid -> out[b][NCOLK].
// NCOLK = nout dimension size; bias indexed by nout.
template <int SLICES, int NOUTDIM, int ACT>
__global__ void epi_kernel(const float* __restrict__ P, const float* __restrict__ bias,
                           float* __restrict__ out) {
    int i = blockIdx.x * blockDim.x + threadIdx.x;
    const int total = NOUTDIM * N_GRAPHS;
    if (i >= total) return;
    int nout = i >> 6;        // /64
    int b = i & 63;
    float v = bias[nout];
#pragma unroll
    for (int s = 0; s < SLICES; s++) v += P[(size_t)s * total + i];
    if (ACT == 1) {
        v = fmaxf(v, 0.0f);
        out[(size_t)b * NOUTDIM + nout] = __uint_as_float(cvt_tf32(v));
    } else {
        out[(size_t)b * NOUTDIM + nout] = 1.0f / (1.0f + expf(-v));
    }
}

// ---------------- GCN GEMM (64x64 tile, legacy, unchanged) ----------------
template <int K, int N>
__global__ void __launch_bounds__(256) gemm_ms(
    const float* __restrict__ A, const float* __restrict__ W,
    float* __restrict__ C) {
    constexpr int KT = K / 32;

    extern __shared__ __align__(16) float smemf[];
    float* AsBase = smemf;
    float* WsBase = smemf + GSTAGES * 64 * 36;

    const int t = threadIdx.x;
    const int n0 = blockIdx.x * 64;
    const int m0 = blockIdx.z * 64;

    const int lane = t & 31, wid = t >> 5;
    const int g = lane >> 2, q = lane & 3;
    const int wm = (wid >> 1) << 4;
    const int wn = (wid & 1) << 5;

    auto As_ = [&](int s, int r, int c) -> float* { return AsBase + ((s * 64 + r) * 36 + c); };
    auto Ws_ = [&](int s, int r, int c) -> float* { return WsBase + ((s * 32 + r) * 72 + c); };

    auto load_stage = [&](int s, int kt) {
        if (kt < KT) {
            const int kk = kt * 32;
#pragma unroll
            for (int i = 0; i < 2; i++) {
                int id = t + i * 256;
                int r = id >> 3, c = id & 7;
                cp_async16(As_(s, r, c * 4), A + (size_t)(m0 + r) * K + kk + c * 4);
            }
#pragma unroll
            for (int i = 0; i < 2; i++) {
                int id = t + i * 256;
                int r = id >> 4, c = id & 15;
                cp_async16(Ws_(s, r, c * 4), W + (size_t)(kk + r) * N + n0 + c * 4);
            }
        }
        cp_commit();
    };

#pragma unroll
    for (int s = 0; s < GSTAGES - 1; s++) load_stage(s, s);

    float acc[4][4] = {};
    int sidx = 0;
    for (int kt = 0; kt < KT; kt++) {
        cp_wait<GSTAGES - 2>();
        __syncthreads();
        int fill = sidx + (GSTAGES - 1);
        if (fill >= GSTAGES) fill -= GSTAGES;
        load_stage(fill, kt + GSTAGES - 1);

        const int bb = sidx;
#pragma unroll
        for (int kk = 0; kk < 4; kk++) {
            const int k8 = kk * 8;
            uint32_t a0 = cvt_tf32(*As_(bb, wm + g, k8 + q));
            uint32_t a1 = cvt_tf32(*As_(bb, wm + g + 8, k8 + q));
            uint32_t a2 = cvt_tf32(*As_(bb, wm + g, k8 + q + 4));
            uint32_t a3 = cvt_tf32(*As_(bb, wm + g + 8, k8 + q + 4));
#pragma unroll
            for (int nf = 0; nf < 4; nf++) {
                uint32_t b0 = cvt_tf32(*Ws_(bb, k8 + q, wn + nf * 8 + g));
                uint32_t b1 = cvt_tf32(*Ws_(bb, k8 + q + 4, wn + nf * 8 + g));
                mma_tf32(acc[nf], a0, a1, a2, a3, b0, b1);
            }
        }
        sidx = sidx + 1 == GSTAGES ? 0 : sidx + 1;
    }

#pragma unroll
    for (int nf = 0; nf < 4; nf++) {
#pragma unroll
        for (int i = 0; i < 4; i++) {
            int row = m0 + wm + g + ((i >> 1) << 3);
            int col = n0 + wn + nf * 8 + q * 2 + (i & 1);
            C[(size_t)row * N + col] = acc[nf][i];
        }
    }
}

// ---------------- big GEMM, weight-as-A formulation ----------------
// D[nout, b] = sum_k W[k, nout] * Z[b, k];  P[ks][nout][64] partials.
// Block: 128 nout x 64 batch, 256 threads = 8 warps as 4m x 2n, warp tile 32x32.
// A = W^T via Ws[32][136] (k-major rows, pad 136 -> bank 8q+g, conflict-free; needs cvt).
// B = Z^T via Zs[64][36]  (b-major rows, pad 36 -> bank 4g+q, conflict-free; Z is
//     pre-rounded tf32 at producers -> raw bits used, NO cvt).
template <int K, int NOUT, int KSLICES>
__global__ void __launch_bounds__(256, 2) gemm_wt(
    const float* __restrict__ Zmat, const float* __restrict__ W,
    float* __restrict__ P) {
    constexpr int KSLICE = K / KSLICES;
    constexpr int KT = KSLICE / 32;
    constexpr int WS_F = 32 * 136;            // 4352 floats
    constexpr int ZS_F = 64 * 36;             // 2304 floats
    constexpr int STG_F = WS_F + ZS_F;        // 6656 floats = 26624 B

    extern __shared__ __align__(16) float smemf[];

    const int t = threadIdx.x;
    const int m0 = blockIdx.x * 128;          // nout tile
    const int ks = blockIdx.y;
    const int kbase = ks * KSLICE;

    const int lane = t & 31, wid = t >> 5;
    const int g = lane >> 2, q = lane & 3;
    const int mB = (wid >> 1) << 5;           // 4 m-warps: 0,32,64,96
    const int nB = (wid & 1) << 5;            // 2 n-warps: 0,32

    auto Ws_ = [&](int s) -> float* { return smemf + s * STG_F; };
    auto Zs_ = [&](int s) -> float* { return smemf + s * STG_F + WS_F; };

    auto load_stage = [&](int s, int kt) {
        if (kt < KT) {
            const int kk = kbase + kt * 32;
            // W: 32 k-rows x 128 floats -> Ws[r][c], 1024 chunks
            float* ws = Ws_(s);
#pragma unroll
            for (int i = 0; i < 4; i++) {
                int id = t + i * 256;
                int r = id >> 5, c = id & 31;
                cp_async16(ws + r * 136 + c * 4, W + (size_t)(kk + r) * NOUT + m0 + c * 4);
            }
            // Z: 64 b-rows x 32 floats -> Zs[b][c], 512 chunks
            float* zs = Zs_(s);
#pragma unroll
            for (int i = 0; i < 2; i++) {
                int id = t + i * 256;
                int b = id >> 3, c = id & 7;
                cp_async16(zs + b * 36 + c * 4, Zmat + (size_t)b * K + kk + c * 4);
            }
        }
        cp_commit();
    };

#pragma unroll
    for (int s = 0; s < WSTAGES - 1; s++) load_stage(s, s);

    float acc[2][4][4] = {};
    int sidx = 0;
    for (int kt = 0; kt < KT; kt++) {
        cp_wait<WSTAGES - 2>();
        __syncthreads();
        int fill = sidx + (WSTAGES - 1);
        if (fill >= WSTAGES) fill -= WSTAGES;
        load_stage(fill, kt + WSTAGES - 1);

        const float* ws = Ws_(sidx);
        const float* zs = Zs_(sidx);
#pragma unroll
        for (int kk = 0; kk < 4; kk++) {
            const int k8 = kk * 8;
            // A fragments: W^T, rows = nout. a(m,k) = Ws[k][m]
            uint32_t a[2][4];
#pragma unroll
            for (int mi = 0; mi < 2; mi++) {
                const int m = mB + mi * 16;
                a[mi][0] = cvt_tf32(ws[(k8 + q) * 136 + m + g]);
                a[mi][1] = cvt_tf32(ws[(k8 + q) * 136 + m + g + 8]);
                a[mi][2] = cvt_tf32(ws[(k8 + q + 4) * 136 + m + g]);
                a[mi][3] = cvt_tf32(ws[(k8 + q + 4) * 136 + m + g + 8]);
            }
            // B fragments: Z^T, cols = batch. b(k,n) = Zs[n][k]; no cvt (pre-rounded)
            uint32_t bf[4][2];
#pragma unroll
            for (int ni = 0; ni < 4; ni++) {
                const int n = nB + ni * 8 + g;
                bf[ni][0] = __float_as_uint(zs[n * 36 + k8 + q]);
                bf[ni][1] = __float_as_uint(zs[n * 36 + k8 + q + 4]);
            }
#pragma unroll
            for (int mi = 0; mi < 2; mi++)
#pragma unroll
                for (int ni = 0; ni < 4; ni++)
                    mma_tf32(acc[mi][ni], a[mi][0], a[mi][1], a[mi][2], a[mi][3],
                             bf[ni][0], bf[ni][1]);
        }
        sidx = sidx + 1 == WSTAGES ? 0 : sidx + 1;
    }

    // epilogue: P[ks][nout][64]
    float* Pout = P + (size_t)ks * ((size_t)NOUT * 64);
#pragma unroll
    for (int mi = 0; mi < 2; mi++) {
#pragma unroll
        for (int ni = 0; ni < 4; ni++) {
#pragma unroll
            for (int i = 0; i < 4; i++) {
                int row = m0 + mB + mi * 16 + g + ((i >> 1) << 3);
                int col = nB + ni * 8 + q * 2 + (i & 1);
                Pout[(size_t)row * 64 + col] = acc[mi][ni][i];
            }
        }
    }
}

#define GEMM_SMEM (GSTAGES * (64 * 36 + 32 * 72) * (int)sizeof(float))     // 55296
#define WT_SMEM   (WSTAGES * (32 * 136 + 64 * 36) * (int)sizeof(float))    // 79872

// ---------------- launch ----------------
extern "C" void kernel_launch(void* const* d_in, const int* in_sizes, int n_in,
                              void* d_out, int out_size) {
    const float* x   = (const float*)d_in[0];
    const int*   ei  = (const int*)d_in[1];
    const float* Wg  = (const float*)d_in[2];
    const float* bg  = (const float*)d_in[3];
    const float* W1  = (const float*)d_in[4];
    const float* b1  = (const float*)d_in[5];
    const float* W2  = (const float*)d_in[6];
    const float* b2  = (const float*)d_in[7];
    float* out = (float*)d_out;

    const int* src = ei;
    const int* dst = ei + N_EDGES;

    float *H, *AGG, *DINV, *ZOUT, *Z2, *Z2P, *OUTP;
    int* DEG;
    cudaGetSymbolAddress((void**)&H, d_H);
    cudaGetSymbolAddress((void**)&AGG, d_AGG);
    cudaGetSymbolAddress((void**)&DEG, d_DEG);
    cudaGetSymbolAddress((void**)&DINV, d_DINV);
    cudaGetSymbolAddress((void**)&ZOUT, d_ZOUT);
    cudaGetSymbolAddress((void**)&Z2, d_Z2);
    cudaGetSymbolAddress((void**)&Z2P, d_Z2P);
    cudaGetSymbolAddress((void**)&OUTP, d_OUTP);

    cudaFuncSetAttribute((const void*)gemm_ms<TBL, LATENT>,
                         cudaFuncAttributeMaxDynamicSharedMemorySize, GEMM_SMEM);
    cudaFuncSetAttribute((const void*)gemm_wt<N2, HID, KS1>,
                         cudaFuncAttributeMaxDynamicSharedMemorySize, WT_SMEM);
    cudaFuncSetAttribute((const void*)gemm_wt<HID, N2, KS2>,
                         cudaFuncAttributeMaxDynamicSharedMemorySize, WT_SMEM);

    // 1. zero scratch
    zero_kernel<<<(N_NODES * LATENT + 255) / 256, 256>>>(AGG, DEG);

    // 2-3. degree + dinv
    deg_kernel<<<(N_EDGES + 255) / 256, 256>>>(dst, DEG);
    dinv_kernel<<<(N_NODES + 255) / 256, 256>>>(DEG, DINV);

    // 4. h = x @ Wg
    gemm_ms<TBL, LATENT><<<dim3(LATENT / 64, 1, N_NODES / 64), 256, GEMM_SMEM>>>(x, Wg, H);

    // 5. scatter
    scatter_kernel<<<N_EDGES / 8, 256>>>(H, src, dst, DINV, AGG);

    // 6. relu + bias
    relu_bias_kernel<<<(N_NODES * LATENT + 255) / 256, 256>>>(AGG, bg);

    // 7. outer products (tf32-rounded output)
    outer_kernel<<<N_GRAPHS, 256>>>(AGG, ZOUT);

    // 8. z2 = relu(zout @ W1 + b1): 100 nout-tiles x 8 k-slices = 800 blocks
    gemm_wt<N2, HID, KS1><<<dim3(HID / 128, KS1), 256, WT_SMEM>>>(ZOUT, W1, Z2P);
    epi_kernel<KS1, HID, 1><<<(HID * N_GRAPHS + 255) / 256, 256>>>(Z2P, b1, Z2);

    // 9. y = sigmoid(z2 @ W2 + b2): 50 nout-tiles x 16 k-slices = 800 blocks
    gemm_wt<HID, N2, KS2><<<dim3(N2 / 128, KS2), 256, WT_SMEM>>>(Z2, W2, OUTP);
    epi_kernel<KS2, N2, 2><<<(N2 * N_GRAPHS + 255) / 256, 256>>>(OUTP, b2, out);
}

// round 13
// speedup vs baseline: 2.0234x; 1.0335x over previous
#include <cuda_runtime.h>
#include <cuda_bf16.h>
#include <cstdint>
#include <cstdio>

// ---------------- problem constants ----------------
#define N_NEURONS 80
#define TBL       256
#define LATENT    128
#define N_GRAPHS  64
#define N_NODES   (N_GRAPHS * N_NEURONS)   // 5120
#define N_EDGES   (N_NODES * 32)           // 163840
#define N2        (N_NEURONS * N_NEURONS)  // 6400
#define HID       (2 * N2)                 // 12800

#define GSTAGES 3     // GCN gemm stages
#define KS1 5         // split-K GEMM1: KSLICE=1280, KT=40, 100x5=500 blocks
#define KS2 10        // split-K GEMM2: KSLICE=1280, KT=40, 50x10=500 blocks

// ---------------- device scratch ----------------
__device__ float d_H[N_NODES * LATENT];
__device__ float d_AGG[N_NODES * LATENT];
__device__ int   d_DEG[N_NODES];
__device__ float d_DINV[N_NODES];
__device__ float d_ZOUT[N_GRAPHS * N2];       // [64][6400], tf32-rounded
__device__ float d_Z2[N_GRAPHS * HID];        // [64][12800], tf32-rounded
__device__ float d_Z2P[KS1 * HID * N_GRAPHS]; // partials [ks][nout][64]
__device__ float d_OUTP[KS2 * N2 * N_GRAPHS]; // partials [ks][nout][64]

// ---------------- PTX helpers ----------------
__device__ __forceinline__ uint32_t cvt_tf32(float x) {
    uint32_t r;
    asm("cvt.rna.tf32.f32 %0, %1;" : "=r"(r) : "f"(x));
    return r;
}

__device__ __forceinline__ void mma_tf32(float c[4],
                                         uint32_t a0, uint32_t a1, uint32_t a2, uint32_t a3,
                                         uint32_t b0, uint32_t b1) {
    asm volatile(
        "mma.sync.aligned.m16n8k8.row.col.f32.tf32.tf32.f32 "
        "{%0,%1,%2,%3},{%4,%5,%6,%7},{%8,%9},{%0,%1,%2,%3};"
        : "+f"(c[0]), "+f"(c[1]), "+f"(c[2]), "+f"(c[3])
        : "r"(a0), "r"(a1), "r"(a2), "r"(a3), "r"(b0), "r"(b1));
}

__device__ __forceinline__ void cp_async16(void* smem_dst, const void* gmem_src) {
    uint32_t s = (uint32_t)__cvta_generic_to_shared(smem_dst);
    asm volatile("cp.async.cg.shared.global [%0], [%1], 16;" :: "r"(s), "l"(gmem_src));
}
__device__ __forceinline__ void cp_commit() { asm volatile("cp.async.commit_group;"); }
template <int NN>
__device__ __forceinline__ void cp_wait() { asm volatile("cp.async.wait_group %0;" :: "n"(NN)); }

// ---------------- small kernels ----------------
__global__ void zero_kernel(float* __restrict__ agg, int* __restrict__ deg) {
    int i = blockIdx.x * blockDim.x + threadIdx.x;
    if (i < N_NODES * LATENT) agg[i] = 0.0f;
    if (i < N_NODES) deg[i] = 0;
}

__global__ void deg_kernel(const int* __restrict__ dst, int* __restrict__ deg) {
    int i = blockIdx.x * blockDim.x + threadIdx.x;
    if (i < N_EDGES) atomicAdd(&deg[dst[i]], 1);
}

__global__ void dinv_kernel(const int* __restrict__ deg, float* __restrict__ dinv) {
    int i = blockIdx.x * blockDim.x + threadIdx.x;
    if (i < N_NODES) {
        int d = deg[i];
        dinv[i] = (d > 0) ? rsqrtf((float)d) : 0.0f;
    }
}

__global__ void __launch_bounds__(256) scatter_kernel(
    const float* __restrict__ H, const int* __restrict__ src, const int* __restrict__ dst,
    const float* __restrict__ dinv, float* __restrict__ agg) {
    int e = (blockIdx.x * blockDim.x + threadIdx.x) >> 5;
    int lane = threadIdx.x & 31;
    if (e >= N_EDGES) return;
    int s = src[e], d = dst[e];
    float nrm = dinv[s] * dinv[d];
    const float4* hp = reinterpret_cast<const float4*>(H + (size_t)s * LATENT);
    float4 v = hp[lane];
    v.x *= nrm; v.y *= nrm; v.z *= nrm; v.w *= nrm;
    float* ap = agg + (size_t)d * LATENT + lane * 4;
    asm volatile("red.global.add.v4.f32 [%0], {%1,%2,%3,%4};"
                 :: "l"(ap), "f"(v.x), "f"(v.y), "f"(v.z), "f"(v.w) : "memory");
}

__global__ void relu_bias_kernel(float* __restrict__ agg, const float* __restrict__ bg) {
    int i = blockIdx.x * blockDim.x + threadIdx.x;
    if (i < N_NODES * LATENT) {
        float v = agg[i] + bg[i & (LATENT - 1)];
        agg[i] = fmaxf(v, 0.0f);
    }
}

// per-graph z zT; output tf32-rounded so big-GEMM B-side reads are cvt-free
__global__ void __launch_bounds__(256) outer_kernel(const float* __restrict__ Z,
                                                    float* __restrict__ Zo) {
    __shared__ float zs[N_NEURONS][LATENT + 1];
    int b = blockIdx.x;
    const float* zb = Z + (size_t)b * N_NEURONS * LATENT;
    for (int i = threadIdx.x; i < N_NEURONS * LATENT; i += 256) {
        zs[i >> 7][i & 127] = zb[i];
    }
    __syncthreads();
    int tx = threadIdx.x & 15, ty = threadIdx.x >> 4;
    int nB = ty * 5, mB = tx * 5;
    float acc[5][5] = {};
    for (int l = 0; l < LATENT; l++) {
        float zn[5], zm[5];
#pragma unroll
        for (int i = 0; i < 5; i++) { zn[i] = zs[nB + i][l]; zm[i] = zs[mB + i][l]; }
#pragma unroll
        for (int i = 0; i < 5; i++)
#pragma unroll
            for (int j = 0; j < 5; j++) acc[i][j] = fmaf(zn[i], zm[j], acc[i][j]);
    }
    float* ob = Zo + (size_t)b * N2;
#pragma unroll
    for (int i = 0; i < 5; i++)
#pragma unroll
        for (int j = 0; j < 5; j++)
            ob[(nB + i) * N_NEURONS + mB + j] = __uint_as_float(cvt_tf32(acc[i][j]));
}

// split-K reduce over transposed partials P[s][nout][64].
// ACT==1: relu + tf32-round -> Z2[b][NOUTDIM]. ACT==2: sigmoid -> out[b][NOUTDIM].
template <int SLICES, int NOUTDIM, int ACT>
__global__ void epi_kernel(const float* __restrict__ P, const float* __restrict__ bias,
                           float* __restrict__ out) {
    int i = blockIdx.x * blockDim.x + threadIdx.x;
    const int total = NOUTDIM * N_GRAPHS;
    if (i >= total) return;
    int nout = i >> 6;        // /64
    int b = i & 63;
    float v = bias[nout];
#pragma unroll
    for (int s = 0; s < SLICES; s++) v += P[(size_t)s * total + i];
    if (ACT == 1) {
        v = fmaxf(v, 0.0f);
        out[(size_t)b * NOUTDIM + nout] = __uint_as_float(cvt_tf32(v));
    } else {
        out[(size_t)b * NOUTDIM + nout] = 1.0f / (1.0f + expf(-v));
    }
}

// ---------------- GCN GEMM (64x64 tile, legacy, unchanged) ----------------
template <int K, int N>
__global__ void __launch_bounds__(256) gemm_ms(
    const float* __restrict__ A, const float* __restrict__ W,
    float* __restrict__ C) {
    constexpr int KT = K / 32;

    extern __shared__ __align__(16) float smemf[];
    float* AsBase = smemf;
    float* WsBase = smemf + GSTAGES * 64 * 36;

    const int t = threadIdx.x;
    const int n0 = blockIdx.x * 64;
    const int m0 = blockIdx.z * 64;

    const int lane = t & 31, wid = t >> 5;
    const int g = lane >> 2, q = lane & 3;
    const int wm = (wid >> 1) << 4;
    const int wn = (wid & 1) << 5;

    auto As_ = [&](int s, int r, int c) -> float* { return AsBase + ((s * 64 + r) * 36 + c); };
    auto Ws_ = [&](int s, int r, int c) -> float* { return WsBase + ((s * 32 + r) * 72 + c); };

    auto load_stage = [&](int s, int kt) {
        if (kt < KT) {
            const int kk = kt * 32;
#pragma unroll
            for (int i = 0; i < 2; i++) {
                int id = t + i * 256;
                int r = id >> 3, c = id & 7;
                cp_async16(As_(s, r, c * 4), A + (size_t)(m0 + r) * K + kk + c * 4);
            }
#pragma unroll
            for (int i = 0; i < 2; i++) {
                int id = t + i * 256;
                int r = id >> 4, c = id & 15;
                cp_async16(Ws_(s, r, c * 4), W + (size_t)(kk + r) * N + n0 + c * 4);
            }
        }
        cp_commit();
    };

#pragma unroll
    for (int s = 0; s < GSTAGES - 1; s++) load_stage(s, s);

    float acc[4][4] = {};
    int sidx = 0;
    for (int kt = 0; kt < KT; kt++) {
        cp_wait<GSTAGES - 2>();
        __syncthreads();
        int fill = sidx + (GSTAGES - 1);
        if (fill >= GSTAGES) fill -= GSTAGES;
        load_stage(fill, kt + GSTAGES - 1);

        const int bb = sidx;
#pragma unroll
        for (int kk = 0; kk < 4; kk++) {
            const int k8 = kk * 8;
            uint32_t a0 = cvt_tf32(*As_(bb, wm + g, k8 + q));
            uint32_t a1 = cvt_tf32(*As_(bb, wm + g + 8, k8 + q));
            uint32_t a2 = cvt_tf32(*As_(bb, wm + g, k8 + q + 4));
            uint32_t a3 = cvt_tf32(*As_(bb, wm + g + 8, k8 + q + 4));
#pragma unroll
            for (int nf = 0; nf < 4; nf++) {
                uint32_t b0 = cvt_tf32(*Ws_(bb, k8 + q, wn + nf * 8 + g));
                uint32_t b1 = cvt_tf32(*Ws_(bb, k8 + q + 4, wn + nf * 8 + g));
                mma_tf32(acc[nf], a0, a1, a2, a3, b0, b1);
            }
        }
        sidx = sidx + 1 == GSTAGES ? 0 : sidx + 1;
    }

#pragma unroll
    for (int nf = 0; nf < 4; nf++) {
#pragma unroll
        for (int i = 0; i < 4; i++) {
            int row = m0 + wm + g + ((i >> 1) << 3);
            int col = n0 + wn + nf * 8 + q * 2 + (i & 1);
            C[(size_t)row * N + col] = acc[nf][i];
        }
    }
}

// ---------------- big GEMM, weight-as-A, 2-stage, 4 blocks/SM ----------------
// D[nout, b] = sum_k W[k, nout] * Z[b, k];  P[ks][nout][64] partials.
// Block: 128 nout x 64 batch, 256 threads = 8 warps (4m x 2n), warp tile 32x32.
// A = W^T via Ws[32][136]: raw f32 bits fed to mma (HW tf32-truncate, no cvt).
// B = Z^T via Zs[64][36]: Z pre-rounded tf32 at producers, raw bits exact.
template <int K, int NOUT, int KSLICES>
__global__ void __launch_bounds__(256, 4) gemm_wt(
    const float* __restrict__ Zmat, const float* __restrict__ W,
    float* __restrict__ P) {
    constexpr int KSLICE = K / KSLICES;
    constexpr int KT = KSLICE / 32;
    constexpr int WS_F = 32 * 136;            // 4352 floats
    constexpr int ZS_F = 64 * 36;             // 2304 floats
    constexpr int STG_F = WS_F + ZS_F;        // 6656 floats = 26624 B

    extern __shared__ __align__(16) float smemf[];

    const int t = threadIdx.x;
    const int m0 = blockIdx.x * 128;          // nout tile
    const int ks = blockIdx.y;
    const int kbase = ks * KSLICE;

    const int lane = t & 31, wid = t >> 5;
    const int g = lane >> 2, q = lane & 3;
    const int mB = (wid >> 1) << 5;           // 4 m-warps: 0,32,64,96
    const int nB = (wid & 1) << 5;            // 2 n-warps: 0,32

    auto Ws_ = [&](int s) -> float* { return smemf + s * STG_F; };
    auto Zs_ = [&](int s) -> float* { return smemf + s * STG_F + WS_F; };

    auto load_stage = [&](int s, int kt) {
        if (kt < KT) {
            const int kk = kbase + kt * 32;
            float* ws = Ws_(s);
#pragma unroll
            for (int i = 0; i < 4; i++) {
                int id = t + i * 256;
                int r = id >> 5, c = id & 31;
                cp_async16(ws + r * 136 + c * 4, W + (size_t)(kk + r) * NOUT + m0 + c * 4);
            }
            float* zs = Zs_(s);
#pragma unroll
            for (int i = 0; i < 2; i++) {
                int id = t + i * 256;
                int b = id >> 3, c = id & 7;
                cp_async16(zs + b * 36 + c * 4, Zmat + (size_t)b * K + kk + c * 4);
            }
        }
        cp_commit();
    };

    load_stage(0, 0);

    float acc[2][4][4] = {};
    for (int kt = 0; kt < KT; kt++) {
        // issue next stage first so it streams during this iteration's compute
        load_stage((kt + 1) & 1, kt + 1);
        cp_wait<1>();        // oldest group (stage kt) complete
        __syncthreads();

        const float* ws = Ws_(kt & 1);
        const float* zs = Zs_(kt & 1);
#pragma unroll
        for (int kk = 0; kk < 4; kk++) {
            const int k8 = kk * 8;
            // A fragments: W^T, rows = nout. a(m,k) = Ws[k][m]; raw bits (HW truncates)
            uint32_t a[2][4];
#pragma unroll
            for (int mi = 0; mi < 2; mi++) {
                const int m = mB + mi * 16;
                a[mi][0] = __float_as_uint(ws[(k8 + q) * 136 + m + g]);
                a[mi][1] = __float_as_uint(ws[(k8 + q) * 136 + m + g + 8]);
                a[mi][2] = __float_as_uint(ws[(k8 + q + 4) * 136 + m + g]);
                a[mi][3] = __float_as_uint(ws[(k8 + q + 4) * 136 + m + g + 8]);
            }
            // B fragments: Z^T, cols = batch; pre-rounded tf32, raw bits exact
            uint32_t bf[4][2];
#pragma unroll
            for (int ni = 0; ni < 4; ni++) {
                const int n = nB + ni * 8 + g;
                bf[ni][0] = __float_as_uint(zs[n * 36 + k8 + q]);
                bf[ni][1] = __float_as_uint(zs[n * 36 + k8 + q + 4]);
            }
#pragma unroll
            for (int mi = 0; mi < 2; mi++)
#pragma unroll
                for (int ni = 0; ni < 4; ni++)
                    mma_tf32(acc[mi][ni], a[mi][0], a[mi][1], a[mi][2], a[mi][3],
                             bf[ni][0], bf[ni][1]);
        }
        __syncthreads();     // all warps done with stage kt before it is overwritten
    }

    // epilogue: P[ks][nout][64]
    float* Pout = P + (size_t)ks * ((size_t)NOUT * 64);
#pragma unroll
    for (int mi = 0; mi < 2; mi++) {
#pragma unroll
        for (int ni = 0; ni < 4; ni++) {
#pragma unroll
            for (int i = 0; i < 4; i++) {
                int row = m0 + mB + mi * 16 + g + ((i >> 1) << 3);
                int col = nB + ni * 8 + q * 2 + (i & 1);
                Pout[(size_t)row * 64 + col] = acc[mi][ni][i];
            }
        }
    }
}

#define GEMM_SMEM (GSTAGES * (64 * 36 + 32 * 72) * (int)sizeof(float))  // 55296
#define WT_SMEM   (2 * (32 * 136 + 64 * 36) * (int)sizeof(float))       // 53248

// ---------------- launch ----------------
extern "C" void kernel_launch(void* const* d_in, const int* in_sizes, int n_in,
                              void* d_out, int out_size) {
    const float* x   = (const float*)d_in[0];
    const int*   ei  = (const int*)d_in[1];
    const float* Wg  = (const float*)d_in[2];
    const float* bg  = (const float*)d_in[3];
    const float* W1  = (const float*)d_in[4];
    const float* b1  = (const float*)d_in[5];
    const float* W2  = (const float*)d_in[6];
    const float* b2  = (const float*)d_in[7];
    float* out = (float*)d_out;

    const int* src = ei;
    const int* dst = ei + N_EDGES;

    float *H, *AGG, *DINV, *ZOUT, *Z2, *Z2P, *OUTP;
    int* DEG;
    cudaGetSymbolAddress((void**)&H, d_H);
    cudaGetSymbolAddress((void**)&AGG, d_AGG);
    cudaGetSymbolAddress((void**)&DEG, d_DEG);
    cudaGetSymbolAddress((void**)&DINV, d_DINV);
    cudaGetSymbolAddress((void**)&ZOUT, d_ZOUT);
    cudaGetSymbolAddress((void**)&Z2, d_Z2);
    cudaGetSymbolAddress((void**)&Z2P, d_Z2P);
    cudaGetSymbolAddress((void**)&OUTP, d_OUTP);

    cudaFuncSetAttribute((const void*)gemm_ms<TBL, LATENT>,
                         cudaFuncAttributeMaxDynamicSharedMemorySize, GEMM_SMEM);
    cudaFuncSetAttribute((const void*)gemm_wt<N2, HID, KS1>,
                         cudaFuncAttributeMaxDynamicSharedMemorySize, WT_SMEM);
    cudaFuncSetAttribute((const void*)gemm_wt<HID, N2, KS2>,
                         cudaFuncAttributeMaxDynamicSharedMemorySize, WT_SMEM);

    // 1. zero scratch
    zero_kernel<<<(N_NODES * LATENT + 255) / 256, 256>>>(AGG, DEG);

    // 2-3. degree + dinv
    deg_kernel<<<(N_EDGES + 255) / 256, 256>>>(dst, DEG);
    dinv_kernel<<<(N_NODES + 255) / 256, 256>>>(DEG, DINV);

    // 4. h = x @ Wg
    gemm_ms<TBL, LATENT><<<dim3(LATENT / 64, 1, N_NODES / 64), 256, GEMM_SMEM>>>(x, Wg, H);

    // 5. scatter
    scatter_kernel<<<N_EDGES / 8, 256>>>(H, src, dst, DINV, AGG);

    // 6. relu + bias
    relu_bias_kernel<<<(N_NODES * LATENT + 255) / 256, 256>>>(AGG, bg);

    // 7. outer products (tf32-rounded output)
    outer_kernel<<<N_GRAPHS, 256>>>(AGG, ZOUT);

    // 8. z2 = relu(zout @ W1 + b1): 100 nout-tiles x 5 k-slices = 500 blocks (1 wave)
    gemm_wt<N2, HID, KS1><<<dim3(HID / 128, KS1), 256, WT_SMEM>>>(ZOUT, W1, Z2P);
    epi_kernel<KS1, HID, 1><<<(HID * N_GRAPHS + 255) / 256, 256>>>(Z2P, b1, Z2);

    // 9. y = sigmoid(z2 @ W2 + b2): 50 nout-tiles x 10 k-slices = 500 blocks (1 wave)
    gemm_wt<HID, N2, KS2><<<dim3(N2 / 128, KS2), 256, WT_SMEM>>>(Z2, W2, OUTP);
    epi_kernel<KS2, N2, 2><<<(N2 * N_GRAPHS + 255) / 256, 256>>>(OUTP, b2, out);
}

// round 16
// speedup vs baseline: 2.0408x; 1.0086x over previous
#include <cuda_runtime.h>
#include <cuda_bf16.h>
#include <cstdint>
#include <cstdio>

// ---------------- problem constants ----------------
#define N_NEURONS 80
#define TBL       256
#define LATENT    128
#define N_GRAPHS  64
#define N_NODES   (N_GRAPHS * N_NEURONS)   // 5120
#define N_EDGES   (N_NODES * 32)           // 163840
#define N2        (N_NEURONS * N_NEURONS)  // 6400
#define HID       (2 * N2)                 // 12800

#define GSTAGES 3     // GCN gemm stages
#define KS1 5         // split-K GEMM1: KSLICE=1280, KT=40, 100x5=500 blocks
#define KS2 10        // split-K GEMM2: KSLICE=1280, KT=40, 50x10=500 blocks

// ---------------- device scratch ----------------
__device__ float d_H[N_NODES * LATENT];
__device__ float d_AGG[N_NODES * LATENT];
__device__ int   d_DEG[N_NODES];
__device__ float d_DINV[N_NODES];
__device__ float d_ZOUT[N_GRAPHS * N2];       // [64][6400], tf32-rounded
__device__ float d_Z2[N_GRAPHS * HID];        // [64][12800], tf32-rounded
__device__ float d_Z2P[KS1 * HID * N_GRAPHS]; // partials [ks][nout][64]
__device__ float d_OUTP[KS2 * N2 * N_GRAPHS]; // partials [ks][nout][64]

// ---------------- PTX helpers ----------------
__device__ __forceinline__ uint32_t cvt_tf32(float x) {
    uint32_t r;
    asm("cvt.rna.tf32.f32 %0, %1;" : "=r"(r) : "f"(x));
    return r;
}

__device__ __forceinline__ void mma_tf32(float c[4],
                                         uint32_t a0, uint32_t a1, uint32_t a2, uint32_t a3,
                                         uint32_t b0, uint32_t b1) {
    asm volatile(
        "mma.sync.aligned.m16n8k8.row.col.f32.tf32.tf32.f32 "
        "{%0,%1,%2,%3},{%4,%5,%6,%7},{%8,%9},{%0,%1,%2,%3};"
        : "+f"(c[0]), "+f"(c[1]), "+f"(c[2]), "+f"(c[3])
        : "r"(a0), "r"(a1), "r"(a2), "r"(a3), "r"(b0), "r"(b1));
}

__device__ __forceinline__ void cp_async16(void* smem_dst, const void* gmem_src) {
    uint32_t s = (uint32_t)__cvta_generic_to_shared(smem_dst);
    asm volatile("cp.async.cg.shared.global [%0], [%1], 16;" :: "r"(s), "l"(gmem_src));
}
__device__ __forceinline__ void cp_commit() { asm volatile("cp.async.commit_group;"); }
template <int NN>
__device__ __forceinline__ void cp_wait() { asm volatile("cp.async.wait_group %0;" :: "n"(NN)); }

// ---------------- small kernels ----------------
__global__ void zero_kernel(float* __restrict__ agg, int* __restrict__ deg) {
    int i = blockIdx.x * blockDim.x + threadIdx.x;
    if (i < N_NODES * LATENT) agg[i] = 0.0f;
    if (i < N_NODES) deg[i] = 0;
}

__global__ void deg_kernel(const int* __restrict__ dst, int* __restrict__ deg) {
    int i = blockIdx.x * blockDim.x + threadIdx.x;
    if (i < N_EDGES) atomicAdd(&deg[dst[i]], 1);
}

__global__ void dinv_kernel(const int* __restrict__ deg, float* __restrict__ dinv) {
    int i = blockIdx.x * blockDim.x + threadIdx.x;
    if (i < N_NODES) {
        int d = deg[i];
        dinv[i] = (d > 0) ? rsqrtf((float)d) : 0.0f;
    }
}

// 4 edges per warp: 4 independent LDG.128 in flight, then 4 REDG.v4
__global__ void __launch_bounds__(256) scatter_kernel(
    const float* __restrict__ H, const int* __restrict__ src, const int* __restrict__ dst,
    const float* __restrict__ dinv, float* __restrict__ agg) {
    int w = (blockIdx.x * blockDim.x + threadIdx.x) >> 5;
    int lane = threadIdx.x & 31;
    int e0 = w * 4;
    if (e0 >= N_EDGES) return;

    int s[4], d[4];
    float nrm[4];
    float4 v[4];
#pragma unroll
    for (int j = 0; j < 4; j++) {
        s[j] = src[e0 + j];
        d[j] = dst[e0 + j];
    }
#pragma unroll
    for (int j = 0; j < 4; j++)
        v[j] = reinterpret_cast<const float4*>(H + (size_t)s[j] * LATENT)[lane];
#pragma unroll
    for (int j = 0; j < 4; j++)
        nrm[j] = dinv[s[j]] * dinv[d[j]];
#pragma unroll
    for (int j = 0; j < 4; j++) {
        float4 t = v[j];
        t.x *= nrm[j]; t.y *= nrm[j]; t.z *= nrm[j]; t.w *= nrm[j];
        float* ap = agg + (size_t)d[j] * LATENT + lane * 4;
        asm volatile("red.global.add.v4.f32 [%0], {%1,%2,%3,%4};"
                     :: "l"(ap), "f"(t.x), "f"(t.y), "f"(t.z), "f"(t.w) : "memory");
    }
}

// fused bias+relu + per-graph z zT, 5 row-tiles x 64 graphs = 320 blocks.
// Each block: load full z_b (relu(agg+bg)) to smem, compute 16 rows x 80 cols.
// Output tf32-rounded so big-GEMM B-side reads are cvt-free.
__global__ void __launch_bounds__(256) outer_kernel(const float* __restrict__ AGG,
                                                    const float* __restrict__ bg,
                                                    float* __restrict__ Zo) {
    __shared__ float zs[N_NEURONS][LATENT + 1];
    const int b = blockIdx.x >> 3;          // 64 graphs (blockIdx.x / 8? no: /5) -- see grid
    const int tile = blockIdx.x - b * 5;    // NOTE: grid.x = 64*5 with b = idx/5
    // (recomputed correctly below)
    const int bb = blockIdx.x / 5;
    const int tt = blockIdx.x % 5;
    const float* ab = AGG + (size_t)bb * N_NEURONS * LATENT;
    (void)b; (void)tile;
    for (int i = threadIdx.x; i < N_NEURONS * LATENT; i += 256) {
        int l = i & 127;
        zs[i >> 7][l] = fmaxf(ab[i] + bg[l], 0.0f);
    }
    __syncthreads();
    const int ty = threadIdx.x >> 4;        // 0..15 -> one row each
    const int tx = threadIdx.x & 15;        // 0..15 -> 5 cols each
    const int row = tt * 16 + ty;
    const int c0 = tx * 5;
    float acc[5] = {};
    for (int l = 0; l < LATENT; l++) {
        float zn = zs[row][l];
        float zm[5];
#pragma unroll
        for (int j = 0; j < 5; j++) zm[j] = zs[c0 + j][l];
#pragma unroll
        for (int j = 0; j < 5; j++) acc[j] = fmaf(zn, zm[j], acc[j]);
    }
    float* ob = Zo + (size_t)bb * N2 + (size_t)row * N_NEURONS;
#pragma unroll
    for (int j = 0; j < 5; j++)
        ob[c0 + j] = __uint_as_float(cvt_tf32(acc[j]));
}

// split-K reduce + transpose epilogue.
// P[s][nout][64] -> out[b][NOUTDIM] (coalesced both sides via smem tile).
// ACT==1: relu + tf32-round. ACT==2: sigmoid.
template <int SLICES, int NOUTDIM, int ACT>
__global__ void __launch_bounds__(256) epi_kernel(const float* __restrict__ P,
                                                  const float* __restrict__ bias,
                                                  float* __restrict__ out) {
    __shared__ float ts[64][65];
    const int n0 = blockIdx.x * 64;         // nout tile
    const int t = threadIdx.x;
    const int r = t >> 2;                   // 0..63 nout row within tile
    const int c0 = (t & 3) * 16;            // 16 b-cols per thread

    float v[16];
    const float bia = bias[n0 + r];
#pragma unroll
    for (int j = 0; j < 16; j++) v[j] = bia;
#pragma unroll
    for (int s = 0; s < SLICES; s++) {
        const float* Ps = P + (size_t)s * ((size_t)NOUTDIM * 64) + (size_t)(n0 + r) * 64 + c0;
#pragma unroll
        for (int j4 = 0; j4 < 4; j4++) {
            float4 p4 = reinterpret_cast<const float4*>(Ps)[j4];
            v[j4 * 4 + 0] += p4.x; v[j4 * 4 + 1] += p4.y;
            v[j4 * 4 + 2] += p4.z; v[j4 * 4 + 3] += p4.w;
        }
    }
#pragma unroll
    for (int j = 0; j < 16; j++) {
        float x = v[j];
        if (ACT == 1) x = __uint_as_float(cvt_tf32(fmaxf(x, 0.0f)));
        else          x = 1.0f / (1.0f + expf(-x));
        ts[r][c0 + j] = x;
    }
    __syncthreads();
    // write: thread t -> batch row b = r, nout chunk c0..c0+15
    const int b = r;
#pragma unroll
    for (int j = 0; j < 16; j++) {
        out[(size_t)b * NOUTDIM + n0 + c0 + j] = ts[c0 + j][b];
    }
}

// ---------------- GCN GEMM (64x64 tile, legacy, unchanged) ----------------
template <int K, int N>
__global__ void __launch_bounds__(256) gemm_ms(
    const float* __restrict__ A, const float* __restrict__ W,
    float* __restrict__ C) {
    constexpr int KT = K / 32;

    extern __shared__ __align__(16) float smemf[];
    float* AsBase = smemf;
    float* WsBase = smemf + GSTAGES * 64 * 36;

    const int t = threadIdx.x;
    const int n0 = blockIdx.x * 64;
    const int m0 = blockIdx.z * 64;

    const int lane = t & 31, wid = t >> 5;
    const int g = lane >> 2, q = lane & 3;
    const int wm = (wid >> 1) << 4;
    const int wn = (wid & 1) << 5;

    auto As_ = [&](int s, int r, int c) -> float* { return AsBase + ((s * 64 + r) * 36 + c); };
    auto Ws_ = [&](int s, int r, int c) -> float* { return WsBase + ((s * 32 + r) * 72 + c); };

    auto load_stage = [&](int s, int kt) {
        if (kt < KT) {
            const int kk = kt * 32;
#pragma unroll
            for (int i = 0; i < 2; i++) {
                int id = t + i * 256;
                int r = id >> 3, c = id & 7;
                cp_async16(As_(s, r, c * 4), A + (size_t)(m0 + r) * K + kk + c * 4);
            }
#pragma unroll
            for (int i = 0; i < 2; i++) {
                int id = t + i * 256;
                int r = id >> 4, c = id & 15;
                cp_async16(Ws_(s, r, c * 4), W + (size_t)(kk + r) * N + n0 + c * 4);
            }
        }
        cp_commit();
    };

#pragma unroll
    for (int s = 0; s < GSTAGES - 1; s++) load_stage(s, s);

    float acc[4][4] = {};
    int sidx = 0;
    for (int kt = 0; kt < KT; kt++) {
        cp_wait<GSTAGES - 2>();
        __syncthreads();
        int fill = sidx + (GSTAGES - 1);
        if (fill >= GSTAGES) fill -= GSTAGES;
        load_stage(fill, kt + GSTAGES - 1);

        const int bb = sidx;
#pragma unroll
        for (int kk = 0; kk < 4; kk++) {
            const int k8 = kk * 8;
            uint32_t a0 = cvt_tf32(*As_(bb, wm + g, k8 + q));
            uint32_t a1 = cvt_tf32(*As_(bb, wm + g + 8, k8 + q));
            uint32_t a2 = cvt_tf32(*As_(bb, wm + g, k8 + q + 4));
            uint32_t a3 = cvt_tf32(*As_(bb, wm + g + 8, k8 + q + 4));
#pragma unroll
            for (int nf = 0; nf < 4; nf++) {
                uint32_t b0 = cvt_tf32(*Ws_(bb, k8 + q, wn + nf * 8 + g));
                uint32_t b1 = cvt_tf32(*Ws_(bb, k8 + q + 4, wn + nf * 8 + g));
                mma_tf32(acc[nf], a0, a1, a2, a3, b0, b1);
            }
        }
        sidx = sidx + 1 == GSTAGES ? 0 : sidx + 1;
    }

#pragma unroll
    for (int nf = 0; nf < 4; nf++) {
#pragma unroll
        for (int i = 0; i < 4; i++) {
            int row = m0 + wm + g + ((i >> 1) << 3);
            int col = n0 + wn + nf * 8 + q * 2 + (i & 1);
            C[(size_t)row * N + col] = acc[nf][i];
        }
    }
}

// ---------------- big GEMM, weight-as-A, 2-stage, 4 blocks/SM ----------------
// D[nout, b] = sum_k W[k, nout] * Z[b, k];  P[ks][nout][64] partials.
// Block: 128 nout x 64 batch, 256 threads = 8 warps (4m x 2n), warp tile 32x32.
// A = W^T via Ws[32][136]: raw f32 bits fed to mma (HW tf32-truncate, no cvt).
// B = Z^T via Zs[64][36]: Z pre-rounded tf32 at producers, raw bits exact.
template <int K, int NOUT, int KSLICES>
__global__ void __launch_bounds__(256, 4) gemm_wt(
    const float* __restrict__ Zmat, const float* __restrict__ W,
    float* __restrict__ P) {
    constexpr int KSLICE = K / KSLICES;
    constexpr int KT = KSLICE / 32;
    constexpr int WS_F = 32 * 136;            // 4352 floats
    constexpr int ZS_F = 64 * 36;             // 2304 floats
    constexpr int STG_F = WS_F + ZS_F;        // 6656 floats = 26624 B

    extern __shared__ __align__(16) float smemf[];

    const int t = threadIdx.x;
    const int m0 = blockIdx.x * 128;          // nout tile
    const int ks = blockIdx.y;
    const int kbase = ks * KSLICE;

    const int lane = t & 31, wid = t >> 5;
    const int g = lane >> 2, q = lane & 3;
    const int mB = (wid >> 1) << 5;           // 4 m-warps: 0,32,64,96
    const int nB = (wid & 1) << 5;            // 2 n-warps: 0,32

    auto Ws_ = [&](int s) -> float* { return smemf + s * STG_F; };
    auto Zs_ = [&](int s) -> float* { return smemf + s * STG_F + WS_F; };

    auto load_stage = [&](int s, int kt) {
        if (kt < KT) {
            const int kk = kbase + kt * 32;
            float* ws = Ws_(s);
#pragma unroll
            for (int i = 0; i < 4; i++) {
                int id = t + i * 256;
                int r = id >> 5, c = id & 31;
                cp_async16(ws + r * 136 + c * 4, W + (size_t)(kk + r) * NOUT + m0 + c * 4);
            }
            float* zs = Zs_(s);
#pragma unroll
            for (int i = 0; i < 2; i++) {
                int id = t + i * 256;
                int b = id >> 3, c = id & 7;
                cp_async16(zs + b * 36 + c * 4, Zmat + (size_t)b * K + kk + c * 4);
            }
        }
        cp_commit();
    };

    load_stage(0, 0);

    float acc[2][4][4] = {};
    for (int kt = 0; kt < KT; kt++) {
        // issue next stage first so it streams during this iteration's compute
        load_stage((kt + 1) & 1, kt + 1);
        cp_wait<1>();        // oldest group (stage kt) complete
        __syncthreads();

        const float* ws = Ws_(kt & 1);
        const float* zs = Zs_(kt & 1);
#pragma unroll
        for (int kk = 0; kk < 4; kk++) {
            const int k8 = kk * 8;
            uint32_t a[2][4];
#pragma unroll
            for (int mi = 0; mi < 2; mi++) {
                const int m = mB + mi * 16;
                a[mi][0] = __float_as_uint(ws[(k8 + q) * 136 + m + g]);
                a[mi][1] = __float_as_uint(ws[(k8 + q) * 136 + m + g + 8]);
                a[mi][2] = __float_as_uint(ws[(k8 + q + 4) * 136 + m + g]);
                a[mi][3] = __float_as_uint(ws[(k8 + q + 4) * 136 + m + g + 8]);
            }
            uint32_t bf[4][2];
#pragma unroll
            for (int ni = 0; ni < 4; ni++) {
                const int n = nB + ni * 8 + g;
                bf[ni][0] = __float_as_uint(zs[n * 36 + k8 + q]);
                bf[ni][1] = __float_as_uint(zs[n * 36 + k8 + q + 4]);
            }
#pragma unroll
            for (int mi = 0; mi < 2; mi++)
#pragma unroll
                for (int ni = 0; ni < 4; ni++)
                    mma_tf32(acc[mi][ni], a[mi][0], a[mi][1], a[mi][2], a[mi][3],
                             bf[ni][0], bf[ni][1]);
        }
        __syncthreads();     // all warps done with stage kt before it is overwritten
    }

    // epilogue: P[ks][nout][64], float2 stores (1 sector per 8-col row segment)
    float* Pout = P + (size_t)ks * ((size_t)NOUT * 64);
#pragma unroll
    for (int mi = 0; mi < 2; mi++) {
#pragma unroll
        for (int ni = 0; ni < 4; ni++) {
#pragma unroll
            for (int h = 0; h < 2; h++) {     // h=0: rows g, h=1: rows g+8
                int row = m0 + mB + mi * 16 + g + h * 8;
                int col = nB + ni * 8 + q * 2;
                float2 v2 = make_float2(acc[mi][ni][h * 2 + 0], acc[mi][ni][h * 2 + 1]);
                *reinterpret_cast<float2*>(Pout + (size_t)row * 64 + col) = v2;
            }
        }
    }
}

#define GEMM_SMEM (GSTAGES * (64 * 36 + 32 * 72) * (int)sizeof(float))  // 55296
#define WT_SMEM   (2 * (32 * 136 + 64 * 36) * (int)sizeof(float))       // 53248

// ---------------- launch ----------------
extern "C" void kernel_launch(void* const* d_in, const int* in_sizes, int n_in,
                              void* d_out, int out_size) {
    const float* x   = (const float*)d_in[0];
    const int*   ei  = (const int*)d_in[1];
    const float* Wg  = (const float*)d_in[2];
    const float* bg  = (const float*)d_in[3];
    const float* W1  = (const float*)d_in[4];
    const float* b1  = (const float*)d_in[5];
    const float* W2  = (const float*)d_in[6];
    const float* b2  = (const float*)d_in[7];
    float* out = (float*)d_out;

    const int* src = ei;
    const int* dst = ei + N_EDGES;

    float *H, *AGG, *DINV, *ZOUT, *Z2, *Z2P, *OUTP;
    int* DEG;
    cudaGetSymbolAddress((void**)&H, d_H);
    cudaGetSymbolAddress((void**)&AGG, d_AGG);
    cudaGetSymbolAddress((void**)&DEG, d_DEG);
    cudaGetSymbolAddress((void**)&DINV, d_DINV);
    cudaGetSymbolAddress((void**)&ZOUT, d_ZOUT);
    cudaGetSymbolAddress((void**)&Z2, d_Z2);
    cudaGetSymbolAddress((void**)&Z2P, d_Z2P);
    cudaGetSymbolAddress((void**)&OUTP, d_OUTP);

    cudaFuncSetAttribute((const void*)gemm_ms<TBL, LATENT>,
                         cudaFuncAttributeMaxDynamicSharedMemorySize, GEMM_SMEM);
    cudaFuncSetAttribute((const void*)gemm_wt<N2, HID, KS1>,
                         cudaFuncAttributeMaxDynamicSharedMemorySize, WT_SMEM);
    cudaFuncSetAttribute((const void*)gemm_wt<HID, N2, KS2>,
                         cudaFuncAttributeMaxDynamicSharedMemorySize, WT_SMEM);

    // 1. zero scratch
    zero_kernel<<<(N_NODES * LATENT + 255) / 256, 256>>>(AGG, DEG);

    // 2-3. degree + dinv
    deg_kernel<<<(N_EDGES + 255) / 256, 256>>>(dst, DEG);
    dinv_kernel<<<(N_NODES + 255) / 256, 256>>>(DEG, DINV);

    // 4. h = x @ Wg
    gemm_ms<TBL, LATENT><<<dim3(LATENT / 64, 1, N_NODES / 64), 256, GEMM_SMEM>>>(x, Wg, H);

    // 5. scatter: 4 edges per warp -> 40960 warps
    scatter_kernel<<<N_EDGES / 32, 256>>>(H, src, dst, DINV, AGG);

    // 6+7. fused bias/relu + outer products, 5 tiles x 64 graphs
    outer_kernel<<<N_GRAPHS * 5, 256>>>(AGG, bg, ZOUT);

    // 8. z2 = relu(zout @ W1 + b1): 100 nout-tiles x 5 k-slices = 500 blocks (1 wave)
    gemm_wt<N2, HID, KS1><<<dim3(HID / 128, KS1), 256, WT_SMEM>>>(ZOUT, W1, Z2P);
    epi_kernel<KS1, HID, 1><<<HID / 64, 256>>>(Z2P, b1, Z2);

    // 9. y = sigmoid(z2 @ W2 + b2): 50 nout-tiles x 10 k-slices = 500 blocks (1 wave)
    gemm_wt<HID, N2, KS2><<<dim3(N2 / 128, KS2), 256, WT_SMEM>>>(Z2, W2, OUTP);
    epi_kernel<KS2, N2, 2><<<N2 / 64, 256>>>(OUTP, b2, out);
}